// round 9
// baseline (speedup 1.0000x reference)
#include <cuda_runtime.h>
#include <cuda_fp16.h>
#include <cstdint>
#include <math.h>

#define D_MODEL 1024
#define SEQ     2048
#define BATCH   4
#define NTOK    (BATCH * SEQ)   /* 8192 */

// ---------------- scratch (device globals; no allocations allowed) ----------
__device__ __half g_xh[NTOK * D_MODEL];
__device__ __half g_posh[SEQ * D_MODEL];
__device__ __half g_wh[5][D_MODEL * D_MODEL];   // Wq,Wk,Wv,Wo,Wp (fp16)
__device__ __half g_qkvh[3 * NTOK * D_MODEL];   // q, k, v contiguous
__device__ __half g_ctxh[NTOK * D_MODEL];
__device__ float  g_p[SEQ * D_MODEL];           // pos projection (fp32)
__device__ float  g_bqkv[3 * D_MODEL];          // bq|bk|bv concatenated

// ============================ helpers =======================================
#define CP_ASYNC16(dst, src) \
    asm volatile("cp.async.cg.shared.global [%0], [%1], 16;" \
                 :: "r"(dst), "l"(src) : "memory")
#define CP_COMMIT() asm volatile("cp.async.commit_group;" ::: "memory")
#define CP_WAIT(n)  asm volatile("cp.async.wait_group %0;" :: "n"(n) : "memory")

#define SW128(off) ((off) ^ (((off) >> 3) & 0x70))

__device__ __forceinline__ uint32_t smem_u32(const void* p) {
    uint32_t a;
    asm("{ .reg .u64 t; cvta.to.shared.u64 t, %1; cvt.u32.u64 %0, t; }"
        : "=r"(a) : "l"(p));
    return a;
}

__device__ __forceinline__ uint32_t pack_half2(float a, float b) {
    __half2 h = __floats2half2_rn(a, b);
    return *(uint32_t*)&h;
}

__device__ __forceinline__ float ex2(float x) {
    float y;
    asm("ex2.approx.ftz.f32 %0, %1;" : "=f"(y) : "f"(x));
    return y;
}

#define LDSM4(r0, r1, r2, r3, addr) \
    asm volatile("ldmatrix.sync.aligned.m8n8.x4.shared.b16 {%0,%1,%2,%3}, [%4];" \
                 : "=r"(r0), "=r"(r1), "=r"(r2), "=r"(r3) : "r"(addr))

#define LDSM4T(r0, r1, r2, r3, addr) \
    asm volatile("ldmatrix.sync.aligned.m8n8.x4.trans.shared.b16 {%0,%1,%2,%3}, [%4];" \
                 : "=r"(r0), "=r"(r1), "=r"(r2), "=r"(r3) : "r"(addr))

#define MMA_F16(c, a0, a1, a2, a3, b0, b1) \
    asm volatile( \
        "mma.sync.aligned.m16n8k16.row.col.f32.f16.f16.f32 " \
        "{%0,%1,%2,%3}, {%4,%5,%6,%7}, {%8,%9}, {%0,%1,%2,%3};" \
        : "+f"((c)[0]), "+f"((c)[1]), "+f"((c)[2]), "+f"((c)[3]) \
        : "r"(a0), "r"(a1), "r"(a2), "r"(a3), "r"(b0), "r"(b1))

// ---------------- fused pack: x, pos, 5 weights -> fp16; bq|bk|bv -> fp32 ---
#define N4_X   (NTOK * D_MODEL / 4)
#define N4_POS (SEQ * D_MODEL / 4)
#define N4_W   (D_MODEL * D_MODEL / 4)
#define N4_TOT (N4_X + N4_POS + 5 * N4_W)

__global__ __launch_bounds__(256) void pack_all_kernel(
    const float* __restrict__ x, const float* __restrict__ pos,
    const float* __restrict__ Wq, const float* __restrict__ Wk,
    const float* __restrict__ Wv, const float* __restrict__ Wo,
    const float* __restrict__ Wp,
    const float* __restrict__ bq, const float* __restrict__ bk,
    const float* __restrict__ bv,
    __half* __restrict__ xh, __half* __restrict__ posh,
    __half* __restrict__ wh, float* __restrict__ bqkv)
{
    int i = blockIdx.x * blockDim.x + threadIdx.x;
    const int stride = gridDim.x * blockDim.x;

    if (i < 3 * D_MODEL / 4) {
        const float* src = (i < 256) ? bq : (i < 512) ? bk : bv;
        ((float4*)bqkv)[i] = ((const float4*)src)[i & 255];
    }

    for (; i < N4_TOT; i += stride) {
        const float* s;
        __half* d;
        int idx;
        if (i < N4_X) {
            s = x; d = xh; idx = i;
        } else if (i < N4_X + N4_POS) {
            s = pos; d = posh; idx = i - N4_X;
        } else {
            int wi = i - N4_X - N4_POS;
            int wsel = wi / N4_W;
            idx = wi - wsel * N4_W;
            s = (wsel == 0) ? Wq : (wsel == 1) ? Wk : (wsel == 2) ? Wv
                : (wsel == 3) ? Wo : Wp;
            d = wh + (size_t)wsel * (D_MODEL * D_MODEL);
        }
        float4 t = ((const float4*)s)[idx];
        uint2 r;
        r.x = pack_half2(t.x, t.y);
        r.y = pack_half2(t.z, t.w);
        ((uint2*)d)[idx] = r;
    }
}

// ============================ fp16 mma GEMM =================================
#define BM 128
#define BN 128
#define BKH 64
#define GSTAGES 4
#define NCHUNK (D_MODEL / BKH)
#define TILE_B (BM * BKH * 2)
#define STG_B  (2 * TILE_B)
#define SM_TOTAL (GSTAGES * STG_B)

__device__ __forceinline__ void gemm_load_chunk(
    const __half* __restrict__ X, const __half* __restrict__ W,
    uint32_t sbase, int stage, int m0, int n0, int kof, int tid)
{
    const uint32_t abase = sbase + stage * STG_B;
    const uint32_t bbase = abase + TILE_B;
#pragma unroll
    for (int i = 0; i < 2; i++) {
        int seg = tid + (i << 9);
        int row = seg >> 3, c16 = seg & 7;
        uint32_t off = row * 128 + c16 * 16;
        CP_ASYNC16(abase + SW128(off),
                   X + (size_t)(m0 + row) * D_MODEL + kof + c16 * 8);
    }
#pragma unroll
    for (int i = 0; i < 2; i++) {
        int seg = tid + (i << 9);
        int row = seg >> 3, c16 = seg & 7;
        uint32_t off = row * 128 + c16 * 16;
        CP_ASYNC16(bbase + SW128(off),
                   W + (size_t)(n0 + row) * D_MODEL + kof + c16 * 8);
    }
}

__global__ __launch_bounds__(512, 1) void gemm_f16_kernel(
    const __half* __restrict__ X, const __half* __restrict__ W,
    const float* __restrict__ bias, const float* __restrict__ P,
    void* __restrict__ Yv, int mode)
{
    extern __shared__ char smem[];
    const uint32_t sb = smem_u32(smem);
    const int tid = threadIdx.x;
    const int lane = tid & 31, wid = tid >> 5;
    const int wm = wid >> 2;
    const int wn = wid & 3;
    const int grp = lane >> 3, lrow = lane & 7;
    const int lq = lane >> 2, lr = lane & 3;
    const int n0 = blockIdx.x * BN;
    const int m0 = blockIdx.y * BM;

    float acc[2][4][4];
#pragma unroll
    for (int f = 0; f < 2; f++)
#pragma unroll
        for (int g = 0; g < 4; g++)
#pragma unroll
            for (int e = 0; e < 4; e++) acc[f][g][e] = 0.f;

#pragma unroll
    for (int c = 0; c < GSTAGES - 1; c++) {
        gemm_load_chunk(X, W, sb, c, m0, n0, c * BKH, tid);
        CP_COMMIT();
    }

    for (int m = 0; m < NCHUNK; m++) {
        CP_WAIT(GSTAGES - 2);
        __syncthreads();

        const int pc = m + GSTAGES - 1;
        if (pc < NCHUNK)
            gemm_load_chunk(X, W, sb, pc & (GSTAGES - 1), m0, n0, pc * BKH, tid);
        CP_COMMIT();

        const uint32_t abase = sb + (m & (GSTAGES - 1)) * STG_B;
        const uint32_t bbase = abase + TILE_B;
#pragma unroll
        for (int ks = 0; ks < 4; ks++) {
            const int kc = ks * 16;
            uint32_t A[2][4], B[2][4];
#pragma unroll
            for (int f = 0; f < 2; f++) {
                const int r = wm * 32 + f * 16 + lrow + (grp & 1) * 8;
                const int c = kc + (grp >> 1) * 8;
                LDSM4(A[f][0], A[f][1], A[f][2], A[f][3],
                      abase + SW128((uint32_t)(r * 128 + c * 2)));
            }
#pragma unroll
            for (int u = 0; u < 2; u++) {
                const int r = wn * 32 + u * 16 + lrow + (grp >> 1) * 8;
                const int c = kc + (grp & 1) * 8;
                LDSM4(B[u][0], B[u][1], B[u][2], B[u][3],
                      bbase + SW128((uint32_t)(r * 128 + c * 2)));
            }
#pragma unroll
            for (int f = 0; f < 2; f++)
#pragma unroll
                for (int u = 0; u < 2; u++) {
                    MMA_F16(acc[f][2 * u],     A[f][0], A[f][1], A[f][2], A[f][3],
                            B[u][0], B[u][1]);
                    MMA_F16(acc[f][2 * u + 1], A[f][0], A[f][1], A[f][2], A[f][3],
                            B[u][2], B[u][3]);
                }
        }
    }

    if (mode == 1) {
        const int buf = n0 >> 10;
        __half* Yh = (__half*)Yv + (size_t)buf * (NTOK * D_MODEL);
        const int addP = (buf == 0);
#pragma unroll
        for (int f = 0; f < 2; f++) {
            const int r0 = m0 + wm * 32 + f * 16 + lq;
#pragma unroll
            for (int g = 0; g < 4; g++) {
                const int nc = n0 + wn * 32 + g * 8 + 2 * lr;
                const int col = nc & 1023;
                float2 bz = *(const float2*)(bias + nc);
                float2 v0, v1;
                v0.x = acc[f][g][0] + bz.x; v0.y = acc[f][g][1] + bz.y;
                v1.x = acc[f][g][2] + bz.x; v1.y = acc[f][g][3] + bz.y;
                if (addP) {
                    float2 p0 = *(const float2*)(P + (size_t)(r0 & (SEQ - 1)) * D_MODEL + col);
                    float2 p1 = *(const float2*)(P + (size_t)((r0 + 8) & (SEQ - 1)) * D_MODEL + col);
                    v0.x += p0.x; v0.y += p0.y;
                    v1.x += p1.x; v1.y += p1.y;
                }
                *(uint32_t*)(Yh + (size_t)r0 * D_MODEL + col) = pack_half2(v0.x, v0.y);
                *(uint32_t*)(Yh + (size_t)(r0 + 8) * D_MODEL + col) = pack_half2(v1.x, v1.y);
            }
        }
    } else {
        float* Yf = (float*)Yv;
#pragma unroll
        for (int f = 0; f < 2; f++) {
            const int r0 = m0 + wm * 32 + f * 16 + lq;
#pragma unroll
            for (int g = 0; g < 4; g++) {
                const int nc = n0 + wn * 32 + g * 8 + 2 * lr;
                float2 bz = *(const float2*)(bias + nc);
                float2 v0, v1;
                v0.x = acc[f][g][0] + bz.x; v0.y = acc[f][g][1] + bz.y;
                v1.x = acc[f][g][2] + bz.x; v1.y = acc[f][g][3] + bz.y;
                *(float2*)(Yf + (size_t)r0 * D_MODEL + nc) = v0;
                *(float2*)(Yf + (size_t)(r0 + 8) * D_MODEL + nc) = v1;
            }
        }
    }
}

// ============================ fp16 flash attention ==========================
// BQ=64 (4 warps x m16), BJ=64, dk=64. 128-thread CTAs -> 3 CTAs/SM.
// Softmax in exp2 domain (scale = 0.125 * log2(e) folded into QK result).
#define BQ 64
#define BJ 64
#define KTILE_B (BJ * 64 * 2)            /* 8192 B per stage */
#define AVB_OFF (2 * KTILE_B)
#define ATT_SMEM (4 * KTILE_B)           /* 32768 B */
#define SM_SCALE 0.18033688011112042f    /* 0.125 * log2(e) */

__global__ __launch_bounds__(128, 3) void flash_f16_kernel(
    const __half* __restrict__ Q, const __half* __restrict__ K,
    const __half* __restrict__ V, __half* __restrict__ O)
{
    extern __shared__ char smem[];
    const uint32_t sb = smem_u32(smem);
    const int tid = threadIdx.x;
    const int lane = tid & 31, w = tid >> 5;
    const int lq = lane >> 2, lr = lane & 3;
    const int grp = lane >> 3, lrow = lane & 7;
    const int qt = gridDim.x - 1 - blockIdx.x;   // heavy tiles first
    const int bh = blockIdx.y;
    const int b = bh >> 4, h = bh & 15;
    const int q0 = qt * BQ;
    const size_t base = ((size_t)b * SEQ) * D_MODEL + h * 64;

    uint32_t qa[4][4];
    {
        const __half* q0p = Q + base + (size_t)(q0 + w * 16 + lq) * D_MODEL;
        const __half* q1p = q0p + 8 * D_MODEL;
#pragma unroll
        for (int ks = 0; ks < 4; ks++) {
            const int c = ks * 16 + 2 * lr;
            qa[ks][0] = *(const uint32_t*)(q0p + c);
            qa[ks][1] = *(const uint32_t*)(q1p + c);
            qa[ks][2] = *(const uint32_t*)(q0p + c + 8);
            qa[ks][3] = *(const uint32_t*)(q1p + c + 8);
        }
    }

    float o[8][4];
#pragma unroll
    for (int g = 0; g < 8; g++)
#pragma unroll
        for (int e = 0; e < 4; e++) o[g][e] = 0.f;
    float m0 = -1e30f, m1 = -1e30f, l0 = 0.f, l1 = 0.f;

    const int nj = qt + 1;

#define LOAD_KV(t_) do {                                                      \
    const int s_ = (t_) & 1;                                                  \
    const __half* kg = K + base + (size_t)((t_) * BJ) * D_MODEL;              \
    const __half* vg = V + base + (size_t)((t_) * BJ) * D_MODEL;              \
    const uint32_t kb = sb + s_ * KTILE_B;                                    \
    const uint32_t vb = sb + AVB_OFF + s_ * KTILE_B;                          \
    _Pragma("unroll")                                                         \
    for (int i_ = 0; i_ < 8; i_++) {                                          \
        int seg = tid + (i_ << 7);          /* 0..1023 */                     \
        int kv = seg >> 9;                  /* 0=K, 1=V */                    \
        int s2 = seg & 511;                                                   \
        int row = s2 >> 3, c16 = s2 & 7;                                      \
        uint32_t off = SW128((uint32_t)(row * 128 + c16 * 16));               \
        const __half* src = (kv ? vg : kg) + (size_t)row * D_MODEL + c16 * 8; \
        CP_ASYNC16((kv ? vb : kb) + off, src);                                \
    }                                                                         \
} while (0)

    LOAD_KV(0);
    CP_COMMIT();

    const int qw = q0 + w * 16;
    const int qmax = qw + 15;

    for (int t = 0; t < nj; t++) {
        CP_WAIT(0);
        __syncthreads();
        if (t + 1 < nj) { LOAD_KV(t + 1); CP_COMMIT(); }

        const uint32_t kbase = sb + (t & 1) * KTILE_B;
        const uint32_t vbase = sb + AVB_OFF + (t & 1) * KTILE_B;
        const int j0 = t * BJ;

        float s[8][4];
#pragma unroll
        for (int g = 0; g < 8; g++) {
            float init = ((j0 + g * 8) <= qmax) ? 0.f : -1e30f;
            s[g][0] = init; s[g][1] = init; s[g][2] = init; s[g][3] = init;
        }
#pragma unroll
        for (int ks = 0; ks < 4; ks++) {
            const int kc = ks * 16;
#pragma unroll
            for (int u = 0; u < 4; u++) {
                if ((j0 + u * 16) > qmax) continue;
                const int r = u * 16 + lrow + (grp >> 1) * 8;
                const int c = kc + (grp & 1) * 8;
                uint32_t b0, b1, b2, b3;
                LDSM4(b0, b1, b2, b3, kbase + SW128((uint32_t)(r * 128 + c * 2)));
                MMA_F16(s[2 * u],     qa[ks][0], qa[ks][1], qa[ks][2], qa[ks][3], b0, b1);
                MMA_F16(s[2 * u + 1], qa[ks][0], qa[ks][1], qa[ks][2], qa[ks][3], b2, b3);
            }
        }

        // scale into exp2 domain + causal element mask
#pragma unroll
        for (int g = 0; g < 8; g++) {
            s[g][0] *= SM_SCALE; s[g][1] *= SM_SCALE;
            s[g][2] *= SM_SCALE; s[g][3] *= SM_SCALE;
        }
        if (j0 + BJ - 1 > qw) {
            const int Q0 = qw + lq, Q1 = Q0 + 8;
#pragma unroll
            for (int g = 0; g < 8; g++) {
                const int jc = j0 + g * 8 + 2 * lr;
                if (jc     > Q0) s[g][0] = -1e30f;
                if (jc + 1 > Q0) s[g][1] = -1e30f;
                if (jc     > Q1) s[g][2] = -1e30f;
                if (jc + 1 > Q1) s[g][3] = -1e30f;
            }
        }

        float mx0 = -1e30f, mx1 = -1e30f;
#pragma unroll
        for (int g = 0; g < 8; g++) {
            mx0 = fmaxf(mx0, fmaxf(s[g][0], s[g][1]));
            mx1 = fmaxf(mx1, fmaxf(s[g][2], s[g][3]));
        }
        mx0 = fmaxf(mx0, __shfl_xor_sync(0xffffffffu, mx0, 1));
        mx0 = fmaxf(mx0, __shfl_xor_sync(0xffffffffu, mx0, 2));
        mx1 = fmaxf(mx1, __shfl_xor_sync(0xffffffffu, mx1, 1));
        mx1 = fmaxf(mx1, __shfl_xor_sync(0xffffffffu, mx1, 2));
        const float mn0 = fmaxf(m0, mx0), mn1 = fmaxf(m1, mx1);
        const float c0 = ex2(m0 - mn0), c1 = ex2(m1 - mn1);
        m0 = mn0; m1 = mn1;
        float sum0 = 0.f, sum1 = 0.f;
#pragma unroll
        for (int g = 0; g < 8; g++) {
            s[g][0] = ex2(s[g][0] - mn0);
            s[g][1] = ex2(s[g][1] - mn0);
            s[g][2] = ex2(s[g][2] - mn1);
            s[g][3] = ex2(s[g][3] - mn1);
            sum0 += s[g][0] + s[g][1];
            sum1 += s[g][2] + s[g][3];
        }
        sum0 += __shfl_xor_sync(0xffffffffu, sum0, 1);
        sum0 += __shfl_xor_sync(0xffffffffu, sum0, 2);
        sum1 += __shfl_xor_sync(0xffffffffu, sum1, 1);
        sum1 += __shfl_xor_sync(0xffffffffu, sum1, 2);
        l0 = l0 * c0 + sum0;
        l1 = l1 * c1 + sum1;
#pragma unroll
        for (int g = 0; g < 8; g++) {
            o[g][0] *= c0; o[g][1] *= c0;
            o[g][2] *= c1; o[g][3] *= c1;
        }

        uint32_t pa[4][4];
#pragma unroll
        for (int u = 0; u < 4; u++) {
            pa[u][0] = pack_half2(s[2 * u][0],     s[2 * u][1]);
            pa[u][1] = pack_half2(s[2 * u][2],     s[2 * u][3]);
            pa[u][2] = pack_half2(s[2 * u + 1][0], s[2 * u + 1][1]);
            pa[u][3] = pack_half2(s[2 * u + 1][2], s[2 * u + 1][3]);
        }

#pragma unroll
        for (int kj = 0; kj < 4; kj++) {
            const int jb = kj * 16;
#pragma unroll
            for (int u = 0; u < 4; u++) {
                const int r = jb + lrow + (grp & 1) * 8;
                const int c = u * 16 + (grp >> 1) * 8;
                uint32_t b0, b1, b2, b3;
                LDSM4T(b0, b1, b2, b3, vbase + SW128((uint32_t)(r * 128 + c * 2)));
                MMA_F16(o[2 * u],     pa[kj][0], pa[kj][1], pa[kj][2], pa[kj][3], b0, b1);
                MMA_F16(o[2 * u + 1], pa[kj][0], pa[kj][1], pa[kj][2], pa[kj][3], b2, b3);
            }
        }
    }

    const float inv0 = 1.f / l0, inv1 = 1.f / l1;
    __half* o0 = O + base + (size_t)(qw + lq) * D_MODEL;
    __half* o1 = o0 + 8 * D_MODEL;
#pragma unroll
    for (int g = 0; g < 8; g++) {
        const int c = g * 8 + 2 * lr;
        *(uint32_t*)(o0 + c) = pack_half2(o[g][0] * inv0, o[g][1] * inv0);
        *(uint32_t*)(o1 + c) = pack_half2(o[g][2] * inv1, o[g][3] * inv1);
    }
}

// ---------------------------------------------------------------------------
extern "C" void kernel_launch(void* const* d_in, const int* in_sizes, int n_in,
                              void* d_out, int out_size)
{
    const float* x   = (const float*)d_in[0];
    const float* pos = (const float*)d_in[1];
    const float* Wq  = (const float*)d_in[2];
    const float* bq  = (const float*)d_in[3];
    const float* Wk  = (const float*)d_in[4];
    const float* bk  = (const float*)d_in[5];
    const float* Wv  = (const float*)d_in[6];
    const float* bv  = (const float*)d_in[7];
    const float* Wp  = (const float*)d_in[8];
    const float* bp  = (const float*)d_in[9];
    const float* Wo  = (const float*)d_in[10];
    const float* bo  = (const float*)d_in[11];
    float* out = (float*)d_out;

    __half *xh, *posh, *wh, *qkvh, *ctxh;
    float *p, *bqkv;
    cudaGetSymbolAddress((void**)&xh,   g_xh);
    cudaGetSymbolAddress((void**)&posh, g_posh);
    cudaGetSymbolAddress((void**)&wh,   g_wh);
    cudaGetSymbolAddress((void**)&qkvh, g_qkvh);
    cudaGetSymbolAddress((void**)&ctxh, g_ctxh);
    cudaGetSymbolAddress((void**)&p,    g_p);
    cudaGetSymbolAddress((void**)&bqkv, g_bqkv);

    __half* wqkvh = wh;                                  // [3072, 1024]
    __half* woh   = wh + 3 * (size_t)D_MODEL * D_MODEL;
    __half* wph   = wh + 4 * (size_t)D_MODEL * D_MODEL;
    __half* qh = qkvh;
    __half* kh = qkvh + 1 * (size_t)NTOK * D_MODEL;
    __half* vh = qkvh + 2 * (size_t)NTOK * D_MODEL;

    static bool attr_done = false;
    if (!attr_done) {
        cudaFuncSetAttribute(gemm_f16_kernel,
                             cudaFuncAttributeMaxDynamicSharedMemorySize, SM_TOTAL);
        cudaFuncSetAttribute(flash_f16_kernel,
                             cudaFuncAttributeMaxDynamicSharedMemorySize, ATT_SMEM);
        attr_done = true;
    }

    pack_all_kernel<<<2960, 256>>>(x, pos, Wq, Wk, Wv, Wo, Wp, bq, bk, bv,
                                   xh, posh, wh, bqkv);

    dim3 blk(512);
    gemm_f16_kernel<<<dim3(8, 16), blk, SM_TOTAL>>>(posh, wph, bp, nullptr, p, 0);
    gemm_f16_kernel<<<dim3(24, 64), blk, SM_TOTAL>>>(xh, wqkvh, bqkv, p, qkvh, 1);
    flash_f16_kernel<<<dim3(SEQ / BQ, BATCH * 16), 128, ATT_SMEM>>>(qh, kh, vh, ctxh);
    gemm_f16_kernel<<<dim3(8, 64), blk, SM_TOTAL>>>(ctxh, woh, bo, nullptr, out, 0);
}

// round 10
// speedup vs baseline: 1.5204x; 1.5204x over previous
#include <cuda_runtime.h>
#include <cuda_fp16.h>
#include <cstdint>
#include <math.h>

#define D_MODEL 1024
#define SEQ     2048
#define BATCH   4
#define NTOK    (BATCH * SEQ)   /* 8192 */

// ---------------- scratch (device globals; no allocations allowed) ----------
__device__ __half g_xh[NTOK * D_MODEL];
__device__ __half g_posh[SEQ * D_MODEL];
__device__ __half g_wh[5][D_MODEL * D_MODEL];   // Wq,Wk,Wv,Wo,Wp (fp16)
__device__ __half g_qkvh[3 * NTOK * D_MODEL];   // q, k, v contiguous
__device__ __half g_ctxh[NTOK * D_MODEL];
__device__ float  g_p[SEQ * D_MODEL];           // pos projection (fp32)
__device__ float  g_bqkv[3 * D_MODEL];          // bq|bk|bv concatenated

// ============================ helpers =======================================
#define CP_ASYNC16(dst, src) \
    asm volatile("cp.async.cg.shared.global [%0], [%1], 16;" \
                 :: "r"(dst), "l"(src) : "memory")
#define CP_COMMIT() asm volatile("cp.async.commit_group;" ::: "memory")
#define CP_WAIT(n)  asm volatile("cp.async.wait_group %0;" :: "n"(n) : "memory")

#define SW128(off) ((off) ^ (((off) >> 3) & 0x70))

__device__ __forceinline__ uint32_t smem_u32(const void* p) {
    uint32_t a;
    asm("{ .reg .u64 t; cvta.to.shared.u64 t, %1; cvt.u32.u64 %0, t; }"
        : "=r"(a) : "l"(p));
    return a;
}

__device__ __forceinline__ uint32_t pack_half2(float a, float b) {
    __half2 h = __floats2half2_rn(a, b);
    return *(uint32_t*)&h;
}

__device__ __forceinline__ float ex2(float x) {
    float y;
    asm("ex2.approx.ftz.f32 %0, %1;" : "=f"(y) : "f"(x));
    return y;
}

#define LDSM4(r0, r1, r2, r3, addr) \
    asm volatile("ldmatrix.sync.aligned.m8n8.x4.shared.b16 {%0,%1,%2,%3}, [%4];" \
                 : "=r"(r0), "=r"(r1), "=r"(r2), "=r"(r3) : "r"(addr))

#define LDSM4T(r0, r1, r2, r3, addr) \
    asm volatile("ldmatrix.sync.aligned.m8n8.x4.trans.shared.b16 {%0,%1,%2,%3}, [%4];" \
                 : "=r"(r0), "=r"(r1), "=r"(r2), "=r"(r3) : "r"(addr))

#define MMA_F16(c, a0, a1, a2, a3, b0, b1) \
    asm volatile( \
        "mma.sync.aligned.m16n8k16.row.col.f32.f16.f16.f32 " \
        "{%0,%1,%2,%3}, {%4,%5,%6,%7}, {%8,%9}, {%0,%1,%2,%3};" \
        : "+f"((c)[0]), "+f"((c)[1]), "+f"((c)[2]), "+f"((c)[3]) \
        : "r"(a0), "r"(a1), "r"(a2), "r"(a3), "r"(b0), "r"(b1))

// ---------------- fused pack: x, pos, 5 weights -> fp16; bq|bk|bv -> fp32 ---
#define N4_X   (NTOK * D_MODEL / 4)
#define N4_POS (SEQ * D_MODEL / 4)
#define N4_W   (D_MODEL * D_MODEL / 4)
#define N4_TOT (N4_X + N4_POS + 5 * N4_W)

__global__ __launch_bounds__(256) void pack_all_kernel(
    const float* __restrict__ x, const float* __restrict__ pos,
    const float* __restrict__ Wq, const float* __restrict__ Wk,
    const float* __restrict__ Wv, const float* __restrict__ Wo,
    const float* __restrict__ Wp,
    const float* __restrict__ bq, const float* __restrict__ bk,
    const float* __restrict__ bv,
    __half* __restrict__ xh, __half* __restrict__ posh,
    __half* __restrict__ wh, float* __restrict__ bqkv)
{
    int i = blockIdx.x * blockDim.x + threadIdx.x;
    const int stride = gridDim.x * blockDim.x;

    if (i < 3 * D_MODEL / 4) {
        const float* src = (i < 256) ? bq : (i < 512) ? bk : bv;
        ((float4*)bqkv)[i] = ((const float4*)src)[i & 255];
    }

    for (; i < N4_TOT; i += stride) {
        const float* s;
        __half* d;
        int idx;
        if (i < N4_X) {
            s = x; d = xh; idx = i;
        } else if (i < N4_X + N4_POS) {
            s = pos; d = posh; idx = i - N4_X;
        } else {
            int wi = i - N4_X - N4_POS;
            int wsel = wi / N4_W;
            idx = wi - wsel * N4_W;
            s = (wsel == 0) ? Wq : (wsel == 1) ? Wk : (wsel == 2) ? Wv
                : (wsel == 3) ? Wo : Wp;
            d = wh + (size_t)wsel * (D_MODEL * D_MODEL);
        }
        float4 t = ((const float4*)s)[idx];
        uint2 r;
        r.x = pack_half2(t.x, t.y);
        r.y = pack_half2(t.z, t.w);
        ((uint2*)d)[idx] = r;
    }
}

// ============================ fp16 mma GEMM =================================
// Tile 128x256x64(half), 512 threads (16 warps, 2 M x 8 N), warp tile 64x32.
// 4-stage cp.async pipeline; ldmatrix.x4 from SW128-swizzled smem.
#define BM 128
#define BN 256
#define BKH 64
#define GSTAGES 4
#define NCHUNK (D_MODEL / BKH)          /* 16 */
#define TILE_A (BM * BKH * 2)           /* 16384 B */
#define TILE_BB (BN * BKH * 2)          /* 32768 B */
#define STG_B  (TILE_A + TILE_BB)       /* 49152 B */
#define SM_TOTAL (GSTAGES * STG_B)      /* 196608 B */

__device__ __forceinline__ void gemm_load_chunk(
    const __half* __restrict__ X, const __half* __restrict__ W,
    uint32_t sbase, int stage, int m0, int n0, int kof, int tid)
{
    const uint32_t abase = sbase + stage * STG_B;
    const uint32_t bbase = abase + TILE_A;
#pragma unroll
    for (int i = 0; i < 2; i++) {
        int seg = tid + (i << 9);
        int row = seg >> 3, c16 = seg & 7;
        uint32_t off = row * 128 + c16 * 16;
        CP_ASYNC16(abase + SW128(off),
                   X + (size_t)(m0 + row) * D_MODEL + kof + c16 * 8);
    }
#pragma unroll
    for (int i = 0; i < 4; i++) {
        int seg = tid + (i << 9);
        int row = seg >> 3, c16 = seg & 7;
        uint32_t off = row * 128 + c16 * 16;
        CP_ASYNC16(bbase + SW128(off),
                   W + (size_t)(n0 + row) * D_MODEL + kof + c16 * 8);
    }
}

__global__ __launch_bounds__(512, 1) void gemm_f16_kernel(
    const __half* __restrict__ X, const __half* __restrict__ W,
    const float* __restrict__ bias, const float* __restrict__ P,
    void* __restrict__ Yv, int mode)
{
    extern __shared__ char smem[];
    const uint32_t sb = smem_u32(smem);
    const int tid = threadIdx.x;
    const int lane = tid & 31, wid = tid >> 5;
    const int wm = wid >> 3;          // 0..1
    const int wn = wid & 7;           // 0..7
    const int grp = lane >> 3, lrow = lane & 7;
    const int lq = lane >> 2, lr = lane & 3;
    const int n0 = blockIdx.x * BN;
    const int m0 = blockIdx.y * BM;

    float acc[4][4][4];
#pragma unroll
    for (int f = 0; f < 4; f++)
#pragma unroll
        for (int g = 0; g < 4; g++)
#pragma unroll
            for (int e = 0; e < 4; e++) acc[f][g][e] = 0.f;

#pragma unroll
    for (int c = 0; c < GSTAGES - 1; c++) {
        gemm_load_chunk(X, W, sb, c, m0, n0, c * BKH, tid);
        CP_COMMIT();
    }

    for (int m = 0; m < NCHUNK; m++) {
        CP_WAIT(GSTAGES - 2);
        __syncthreads();

        const int pc = m + GSTAGES - 1;
        if (pc < NCHUNK)
            gemm_load_chunk(X, W, sb, pc & (GSTAGES - 1), m0, n0, pc * BKH, tid);
        CP_COMMIT();

        const uint32_t abase = sb + (m & (GSTAGES - 1)) * STG_B;
        const uint32_t bbase = abase + TILE_A;
#pragma unroll
        for (int ks = 0; ks < 4; ks++) {
            const int kc = ks * 16;
            uint32_t A[4][4], B[2][4];
#pragma unroll
            for (int f = 0; f < 4; f++) {
                const int r = wm * 64 + f * 16 + lrow + (grp & 1) * 8;
                const int c = kc + (grp >> 1) * 8;
                LDSM4(A[f][0], A[f][1], A[f][2], A[f][3],
                      abase + SW128((uint32_t)(r * 128 + c * 2)));
            }
#pragma unroll
            for (int u = 0; u < 2; u++) {
                const int r = wn * 32 + u * 16 + lrow + (grp >> 1) * 8;
                const int c = kc + (grp & 1) * 8;
                LDSM4(B[u][0], B[u][1], B[u][2], B[u][3],
                      bbase + SW128((uint32_t)(r * 128 + c * 2)));
            }
#pragma unroll
            for (int f = 0; f < 4; f++)
#pragma unroll
                for (int u = 0; u < 2; u++) {
                    MMA_F16(acc[f][2 * u],     A[f][0], A[f][1], A[f][2], A[f][3],
                            B[u][0], B[u][1]);
                    MMA_F16(acc[f][2 * u + 1], A[f][0], A[f][1], A[f][2], A[f][3],
                            B[u][2], B[u][3]);
                }
        }
    }

    if (mode == 1) {
        // fused QKV epilogue: each 256-col block lies wholly in one of q/k/v
        const int buf = n0 >> 10;
        __half* Yh = (__half*)Yv + (size_t)buf * (NTOK * D_MODEL);
        const int addP = (buf == 0);
#pragma unroll
        for (int f = 0; f < 4; f++) {
            const int r0 = m0 + wm * 64 + f * 16 + lq;
#pragma unroll
            for (int g = 0; g < 4; g++) {
                const int nc = n0 + wn * 32 + g * 8 + 2 * lr;
                const int col = nc & 1023;
                float2 bz = *(const float2*)(bias + nc);
                float2 v0, v1;
                v0.x = acc[f][g][0] + bz.x; v0.y = acc[f][g][1] + bz.y;
                v1.x = acc[f][g][2] + bz.x; v1.y = acc[f][g][3] + bz.y;
                if (addP) {
                    float2 p0 = *(const float2*)(P + (size_t)(r0 & (SEQ - 1)) * D_MODEL + col);
                    float2 p1 = *(const float2*)(P + (size_t)((r0 + 8) & (SEQ - 1)) * D_MODEL + col);
                    v0.x += p0.x; v0.y += p0.y;
                    v1.x += p1.x; v1.y += p1.y;
                }
                *(uint32_t*)(Yh + (size_t)r0 * D_MODEL + col) = pack_half2(v0.x, v0.y);
                *(uint32_t*)(Yh + (size_t)(r0 + 8) * D_MODEL + col) = pack_half2(v1.x, v1.y);
            }
        }
    } else {
        float* Yf = (float*)Yv;
#pragma unroll
        for (int f = 0; f < 4; f++) {
            const int r0 = m0 + wm * 64 + f * 16 + lq;
#pragma unroll
            for (int g = 0; g < 4; g++) {
                const int nc = n0 + wn * 32 + g * 8 + 2 * lr;
                float2 bz = *(const float2*)(bias + nc);
                float2 v0, v1;
                v0.x = acc[f][g][0] + bz.x; v0.y = acc[f][g][1] + bz.y;
                v1.x = acc[f][g][2] + bz.x; v1.y = acc[f][g][3] + bz.y;
                *(float2*)(Yf + (size_t)r0 * D_MODEL + nc) = v0;
                *(float2*)(Yf + (size_t)(r0 + 8) * D_MODEL + nc) = v1;
            }
        }
    }
}

// ============================ fp16 flash attention ==========================
// R8 structure: BQ=128 (8 warps x m16), BJ=64, dk=64, 256 threads.
// Softmax in exp2 domain (scale = 0.125 * log2(e) folded in after QK^T).
#define BQ 128
#define BJ 64
#define KTILE_B (BJ * 64 * 2)            /* 8192 B per stage */
#define AVB_OFF (2 * KTILE_B)
#define ATT_SMEM (4 * KTILE_B)           /* 32768 B */
#define SM_SCALE 0.18033688011112042f    /* 0.125 * log2(e) */

__global__ __launch_bounds__(256, 1) void flash_f16_kernel(
    const __half* __restrict__ Q, const __half* __restrict__ K,
    const __half* __restrict__ V, __half* __restrict__ O)
{
    extern __shared__ char smem[];
    const uint32_t sb = smem_u32(smem);
    const int tid = threadIdx.x;
    const int lane = tid & 31, w = tid >> 5;
    const int lq = lane >> 2, lr = lane & 3;
    const int grp = lane >> 3, lrow = lane & 7;
    const int qt = gridDim.x - 1 - blockIdx.x;   // heavy tiles first
    const int bh = blockIdx.y;
    const int b = bh >> 4, h = bh & 15;
    const int q0 = qt * BQ;
    const size_t base = ((size_t)b * SEQ) * D_MODEL + h * 64;

    uint32_t qa[4][4];
    {
        const __half* q0p = Q + base + (size_t)(q0 + w * 16 + lq) * D_MODEL;
        const __half* q1p = q0p + 8 * D_MODEL;
#pragma unroll
        for (int ks = 0; ks < 4; ks++) {
            const int c = ks * 16 + 2 * lr;
            qa[ks][0] = *(const uint32_t*)(q0p + c);
            qa[ks][1] = *(const uint32_t*)(q1p + c);
            qa[ks][2] = *(const uint32_t*)(q0p + c + 8);
            qa[ks][3] = *(const uint32_t*)(q1p + c + 8);
        }
    }

    float o[8][4];
#pragma unroll
    for (int g = 0; g < 8; g++)
#pragma unroll
        for (int e = 0; e < 4; e++) o[g][e] = 0.f;
    float m0 = -1e30f, m1 = -1e30f, l0 = 0.f, l1 = 0.f;

    const int nj = qt * 2 + 2;

#define LOAD_KV(t_) do {                                                      \
    const int s_ = (t_) & 1;                                                  \
    const __half* kg = K + base + (size_t)((t_) * BJ) * D_MODEL;              \
    const __half* vg = V + base + (size_t)((t_) * BJ) * D_MODEL;              \
    const uint32_t kb = sb + s_ * KTILE_B;                                    \
    const uint32_t vb = sb + AVB_OFF + s_ * KTILE_B;                          \
    _Pragma("unroll")                                                         \
    for (int i_ = 0; i_ < 4; i_++) {                                          \
        int seg = tid + (i_ << 8);          /* 0..1023 */                     \
        int kv = seg >> 9;                  /* 0=K, 1=V */                    \
        int s2 = seg & 511;                                                   \
        int row = s2 >> 3, c16 = s2 & 7;                                      \
        uint32_t off = SW128((uint32_t)(row * 128 + c16 * 16));               \
        const __half* src = (kv ? vg : kg) + (size_t)row * D_MODEL + c16 * 8; \
        CP_ASYNC16((kv ? vb : kb) + off, src);                                \
    }                                                                         \
} while (0)

    LOAD_KV(0);
    CP_COMMIT();

    const int qw = q0 + w * 16;
    const int qmax = qw + 15;

    for (int t = 0; t < nj; t++) {
        CP_WAIT(0);
        __syncthreads();
        if (t + 1 < nj) { LOAD_KV(t + 1); CP_COMMIT(); }

        const uint32_t kbase = sb + (t & 1) * KTILE_B;
        const uint32_t vbase = sb + AVB_OFF + (t & 1) * KTILE_B;
        const int j0 = t * BJ;

        float s[8][4];
#pragma unroll
        for (int g = 0; g < 8; g++) {
            float init = ((j0 + g * 8) <= qmax) ? 0.f : -1e30f;
            s[g][0] = init; s[g][1] = init; s[g][2] = init; s[g][3] = init;
        }
#pragma unroll
        for (int ks = 0; ks < 4; ks++) {
            const int kc = ks * 16;
#pragma unroll
            for (int u = 0; u < 4; u++) {
                if ((j0 + u * 16) > qmax) continue;
                const int r = u * 16 + lrow + (grp >> 1) * 8;
                const int c = kc + (grp & 1) * 8;
                uint32_t b0, b1, b2, b3;
                LDSM4(b0, b1, b2, b3, kbase + SW128((uint32_t)(r * 128 + c * 2)));
                MMA_F16(s[2 * u],     qa[ks][0], qa[ks][1], qa[ks][2], qa[ks][3], b0, b1);
                MMA_F16(s[2 * u + 1], qa[ks][0], qa[ks][1], qa[ks][2], qa[ks][3], b2, b3);
            }
        }

        // scale into exp2 domain + causal element mask
#pragma unroll
        for (int g = 0; g < 8; g++) {
            s[g][0] *= SM_SCALE; s[g][1] *= SM_SCALE;
            s[g][2] *= SM_SCALE; s[g][3] *= SM_SCALE;
        }
        if (j0 + BJ - 1 > qw) {
            const int Q0 = qw + lq, Q1 = Q0 + 8;
#pragma unroll
            for (int g = 0; g < 8; g++) {
                const int jc = j0 + g * 8 + 2 * lr;
                if (jc     > Q0) s[g][0] = -1e30f;
                if (jc + 1 > Q0) s[g][1] = -1e30f;
                if (jc     > Q1) s[g][2] = -1e30f;
                if (jc + 1 > Q1) s[g][3] = -1e30f;
            }
        }

        float mx0 = -1e30f, mx1 = -1e30f;
#pragma unroll
        for (int g = 0; g < 8; g++) {
            mx0 = fmaxf(mx0, fmaxf(s[g][0], s[g][1]));
            mx1 = fmaxf(mx1, fmaxf(s[g][2], s[g][3]));
        }
        mx0 = fmaxf(mx0, __shfl_xor_sync(0xffffffffu, mx0, 1));
        mx0 = fmaxf(mx0, __shfl_xor_sync(0xffffffffu, mx0, 2));
        mx1 = fmaxf(mx1, __shfl_xor_sync(0xffffffffu, mx1, 1));
        mx1 = fmaxf(mx1, __shfl_xor_sync(0xffffffffu, mx1, 2));
        const float mn0 = fmaxf(m0, mx0), mn1 = fmaxf(m1, mx1);
        const float c0 = ex2(m0 - mn0), c1 = ex2(m1 - mn1);
        m0 = mn0; m1 = mn1;
        float sum0 = 0.f, sum1 = 0.f;
#pragma unroll
        for (int g = 0; g < 8; g++) {
            s[g][0] = ex2(s[g][0] - mn0);
            s[g][1] = ex2(s[g][1] - mn0);
            s[g][2] = ex2(s[g][2] - mn1);
            s[g][3] = ex2(s[g][3] - mn1);
            sum0 += s[g][0] + s[g][1];
            sum1 += s[g][2] + s[g][3];
        }
        sum0 += __shfl_xor_sync(0xffffffffu, sum0, 1);
        sum0 += __shfl_xor_sync(0xffffffffu, sum0, 2);
        sum1 += __shfl_xor_sync(0xffffffffu, sum1, 1);
        sum1 += __shfl_xor_sync(0xffffffffu, sum1, 2);
        l0 = l0 * c0 + sum0;
        l1 = l1 * c1 + sum1;
#pragma unroll
        for (int g = 0; g < 8; g++) {
            o[g][0] *= c0; o[g][1] *= c0;
            o[g][2] *= c1; o[g][3] *= c1;
        }

        uint32_t pa[4][4];
#pragma unroll
        for (int u = 0; u < 4; u++) {
            pa[u][0] = pack_half2(s[2 * u][0],     s[2 * u][1]);
            pa[u][1] = pack_half2(s[2 * u][2],     s[2 * u][3]);
            pa[u][2] = pack_half2(s[2 * u + 1][0], s[2 * u + 1][1]);
            pa[u][3] = pack_half2(s[2 * u + 1][2], s[2 * u + 1][3]);
        }

#pragma unroll
        for (int kj = 0; kj < 4; kj++) {
            const int jb = kj * 16;
#pragma unroll
            for (int u = 0; u < 4; u++) {
                const int r = jb + lrow + (grp & 1) * 8;
                const int c = u * 16 + (grp >> 1) * 8;
                uint32_t b0, b1, b2, b3;
                LDSM4T(b0, b1, b2, b3, vbase + SW128((uint32_t)(r * 128 + c * 2)));
                MMA_F16(o[2 * u],     pa[kj][0], pa[kj][1], pa[kj][2], pa[kj][3], b0, b1);
                MMA_F16(o[2 * u + 1], pa[kj][0], pa[kj][1], pa[kj][2], pa[kj][3], b2, b3);
            }
        }
    }

    const float inv0 = 1.f / l0, inv1 = 1.f / l1;
    __half* o0 = O + base + (size_t)(qw + lq) * D_MODEL;
    __half* o1 = o0 + 8 * D_MODEL;
#pragma unroll
    for (int g = 0; g < 8; g++) {
        const int c = g * 8 + 2 * lr;
        *(uint32_t*)(o0 + c) = pack_half2(o[g][0] * inv0, o[g][1] * inv0);
        *(uint32_t*)(o1 + c) = pack_half2(o[g][2] * inv1, o[g][3] * inv1);
    }
}

// ---------------------------------------------------------------------------
extern "C" void kernel_launch(void* const* d_in, const int* in_sizes, int n_in,
                              void* d_out, int out_size)
{
    const float* x   = (const float*)d_in[0];
    const float* pos = (const float*)d_in[1];
    const float* Wq  = (const float*)d_in[2];
    const float* bq  = (const float*)d_in[3];
    const float* Wk  = (const float*)d_in[4];
    const float* bk  = (const float*)d_in[5];
    const float* Wv  = (const float*)d_in[6];
    const float* bv  = (const float*)d_in[7];
    const float* Wp  = (const float*)d_in[8];
    const float* bp  = (const float*)d_in[9];
    const float* Wo  = (const float*)d_in[10];
    const float* bo  = (const float*)d_in[11];
    float* out = (float*)d_out;

    __half *xh, *posh, *wh, *qkvh, *ctxh;
    float *p, *bqkv;
    cudaGetSymbolAddress((void**)&xh,   g_xh);
    cudaGetSymbolAddress((void**)&posh, g_posh);
    cudaGetSymbolAddress((void**)&wh,   g_wh);
    cudaGetSymbolAddress((void**)&qkvh, g_qkvh);
    cudaGetSymbolAddress((void**)&ctxh, g_ctxh);
    cudaGetSymbolAddress((void**)&p,    g_p);
    cudaGetSymbolAddress((void**)&bqkv, g_bqkv);

    __half* wqkvh = wh;                                  // [3072, 1024]
    __half* woh   = wh + 3 * (size_t)D_MODEL * D_MODEL;
    __half* wph   = wh + 4 * (size_t)D_MODEL * D_MODEL;
    __half* qh = qkvh;
    __half* kh = qkvh + 1 * (size_t)NTOK * D_MODEL;
    __half* vh = qkvh + 2 * (size_t)NTOK * D_MODEL;

    static bool attr_done = false;
    if (!attr_done) {
        cudaFuncSetAttribute(gemm_f16_kernel,
                             cudaFuncAttributeMaxDynamicSharedMemorySize, SM_TOTAL);
        cudaFuncSetAttribute(flash_f16_kernel,
                             cudaFuncAttributeMaxDynamicSharedMemorySize, ATT_SMEM);
        attr_done = true;
    }

    pack_all_kernel<<<2960, 256>>>(x, pos, Wq, Wk, Wv, Wo, Wp, bq, bk, bv,
                                   xh, posh, wh, bqkv);

    dim3 blk(512);
    // p = pos @ Wp^T + bp (fp32): [2048, 1024]
    gemm_f16_kernel<<<dim3(4, 16), blk, SM_TOTAL>>>(posh, wph, bp, nullptr, p, 0);
    // fused QKV: [8192, 3072]
    gemm_f16_kernel<<<dim3(12, 64), blk, SM_TOTAL>>>(xh, wqkvh, bqkv, p, qkvh, 1);
    // attention -> ctx (fp16)
    flash_f16_kernel<<<dim3(SEQ / BQ, BATCH * 16), 256, ATT_SMEM>>>(qh, kh, vh, ctxh);
    // out = ctx @ Wo^T + bo (fp32): [8192, 1024]
    gemm_f16_kernel<<<dim3(4, 64), blk, SM_TOTAL>>>(ctxh, woh, bo, nullptr, out, 0);
}

// round 11
// speedup vs baseline: 1.5645x; 1.0290x over previous
#include <cuda_runtime.h>
#include <cuda_fp16.h>
#include <cstdint>
#include <math.h>

#define D_MODEL 1024
#define SEQ     2048
#define BATCH   4
#define NTOK    (BATCH * SEQ)   /* 8192 */

// ---------------- scratch (device globals; no allocations allowed) ----------
__device__ __half g_xh[NTOK * D_MODEL];
__device__ __half g_posh[SEQ * D_MODEL];
__device__ __half g_wh[5][D_MODEL * D_MODEL];   // Wq,Wk,Wv,Wo,Wp (fp16)
__device__ __half g_qkvh[3 * NTOK * D_MODEL];   // q, k, v contiguous
__device__ __half g_ctxh[NTOK * D_MODEL];
__device__ float  g_p[SEQ * D_MODEL];           // pos projection (fp32)
__device__ float  g_bqkv[3 * D_MODEL];          // bq|bk|bv concatenated

// ============================ helpers =======================================
#define CP_ASYNC16(dst, src) \
    asm volatile("cp.async.cg.shared.global [%0], [%1], 16;" \
                 :: "r"(dst), "l"(src) : "memory")
#define CP_COMMIT() asm volatile("cp.async.commit_group;" ::: "memory")
#define CP_WAIT(n)  asm volatile("cp.async.wait_group %0;" :: "n"(n) : "memory")

#define SW128(off) ((off) ^ (((off) >> 3) & 0x70))

__device__ __forceinline__ uint32_t smem_u32(const void* p) {
    uint32_t a;
    asm("{ .reg .u64 t; cvta.to.shared.u64 t, %1; cvt.u32.u64 %0, t; }"
        : "=r"(a) : "l"(p));
    return a;
}

__device__ __forceinline__ uint32_t pack_half2(float a, float b) {
    __half2 h = __floats2half2_rn(a, b);
    return *(uint32_t*)&h;
}

__device__ __forceinline__ float ex2(float x) {
    float y;
    asm("ex2.approx.ftz.f32 %0, %1;" : "=f"(y) : "f"(x));
    return y;
}

#define LDSM4(r0, r1, r2, r3, addr) \
    asm volatile("ldmatrix.sync.aligned.m8n8.x4.shared.b16 {%0,%1,%2,%3}, [%4];" \
                 : "=r"(r0), "=r"(r1), "=r"(r2), "=r"(r3) : "r"(addr))

#define LDSM4T(r0, r1, r2, r3, addr) \
    asm volatile("ldmatrix.sync.aligned.m8n8.x4.trans.shared.b16 {%0,%1,%2,%3}, [%4];" \
                 : "=r"(r0), "=r"(r1), "=r"(r2), "=r"(r3) : "r"(addr))

#define MMA_F16(c, a0, a1, a2, a3, b0, b1) \
    asm volatile( \
        "mma.sync.aligned.m16n8k16.row.col.f32.f16.f16.f32 " \
        "{%0,%1,%2,%3}, {%4,%5,%6,%7}, {%8,%9}, {%0,%1,%2,%3};" \
        : "+f"((c)[0]), "+f"((c)[1]), "+f"((c)[2]), "+f"((c)[3]) \
        : "r"(a0), "r"(a1), "r"(a2), "r"(a3), "r"(b0), "r"(b1))

// ---------------- fused pack: x, pos, 5 weights -> fp16; bq|bk|bv -> fp32 ---
#define N4_X   (NTOK * D_MODEL / 4)
#define N4_POS (SEQ * D_MODEL / 4)
#define N4_W   (D_MODEL * D_MODEL / 4)
#define N4_TOT (N4_X + N4_POS + 5 * N4_W)

__global__ __launch_bounds__(256) void pack_all_kernel(
    const float* __restrict__ x, const float* __restrict__ pos,
    const float* __restrict__ Wq, const float* __restrict__ Wk,
    const float* __restrict__ Wv, const float* __restrict__ Wo,
    const float* __restrict__ Wp,
    const float* __restrict__ bq, const float* __restrict__ bk,
    const float* __restrict__ bv,
    __half* __restrict__ xh, __half* __restrict__ posh,
    __half* __restrict__ wh, float* __restrict__ bqkv)
{
    int i = blockIdx.x * blockDim.x + threadIdx.x;
    const int stride = gridDim.x * blockDim.x;

    if (i < 3 * D_MODEL / 4) {
        const float* src = (i < 256) ? bq : (i < 512) ? bk : bv;
        ((float4*)bqkv)[i] = ((const float4*)src)[i & 255];
    }

    for (; i < N4_TOT; i += stride) {
        const float* s;
        __half* d;
        int idx;
        if (i < N4_X) {
            s = x; d = xh; idx = i;
        } else if (i < N4_X + N4_POS) {
            s = pos; d = posh; idx = i - N4_X;
        } else {
            int wi = i - N4_X - N4_POS;
            int wsel = wi / N4_W;
            idx = wi - wsel * N4_W;
            s = (wsel == 0) ? Wq : (wsel == 1) ? Wk : (wsel == 2) ? Wv
                : (wsel == 3) ? Wo : Wp;
            d = wh + (size_t)wsel * (D_MODEL * D_MODEL);
        }
        float4 t = ((const float4*)s)[idx];
        uint2 r;
        r.x = pack_half2(t.x, t.y);
        r.y = pack_half2(t.z, t.w);
        ((uint2*)d)[idx] = r;
    }
}

// ============================ fp16 mma GEMM =================================
// Tile 128x256x64(half), 512 threads (16 warps, 2 M x 8 N), warp tile 64x32.
#define BM 128
#define BN 256
#define BKH 64
#define GSTAGES 4
#define NCHUNK (D_MODEL / BKH)          /* 16 */
#define TILE_A (BM * BKH * 2)           /* 16384 B */
#define TILE_BB (BN * BKH * 2)          /* 32768 B */
#define STG_B  (TILE_A + TILE_BB)       /* 49152 B */
#define SM_TOTAL (GSTAGES * STG_B)      /* 196608 B */

__device__ __forceinline__ void gemm_load_chunk(
    const __half* __restrict__ X, const __half* __restrict__ W,
    uint32_t sbase, int stage, int m0, int n0, int kof, int tid)
{
    const uint32_t abase = sbase + stage * STG_B;
    const uint32_t bbase = abase + TILE_A;
#pragma unroll
    for (int i = 0; i < 2; i++) {
        int seg = tid + (i << 9);
        int row = seg >> 3, c16 = seg & 7;
        uint32_t off = row * 128 + c16 * 16;
        CP_ASYNC16(abase + SW128(off),
                   X + (size_t)(m0 + row) * D_MODEL + kof + c16 * 8);
    }
#pragma unroll
    for (int i = 0; i < 4; i++) {
        int seg = tid + (i << 9);
        int row = seg >> 3, c16 = seg & 7;
        uint32_t off = row * 128 + c16 * 16;
        CP_ASYNC16(bbase + SW128(off),
                   W + (size_t)(n0 + row) * D_MODEL + kof + c16 * 8);
    }
}

__global__ __launch_bounds__(512, 1) void gemm_f16_kernel(
    const __half* __restrict__ X, const __half* __restrict__ W,
    const float* __restrict__ bias, const float* __restrict__ P,
    void* __restrict__ Yv, int mode)
{
    extern __shared__ char smem[];
    const uint32_t sb = smem_u32(smem);
    const int tid = threadIdx.x;
    const int lane = tid & 31, wid = tid >> 5;
    const int wm = wid >> 3;          // 0..1
    const int wn = wid & 7;           // 0..7
    const int grp = lane >> 3, lrow = lane & 7;
    const int lq = lane >> 2, lr = lane & 3;
    const int n0 = blockIdx.x * BN;
    const int m0 = blockIdx.y * BM;

    float acc[4][4][4];
#pragma unroll
    for (int f = 0; f < 4; f++)
#pragma unroll
        for (int g = 0; g < 4; g++)
#pragma unroll
            for (int e = 0; e < 4; e++) acc[f][g][e] = 0.f;

#pragma unroll
    for (int c = 0; c < GSTAGES - 1; c++) {
        gemm_load_chunk(X, W, sb, c, m0, n0, c * BKH, tid);
        CP_COMMIT();
    }

    for (int m = 0; m < NCHUNK; m++) {
        CP_WAIT(GSTAGES - 2);
        __syncthreads();

        const int pc = m + GSTAGES - 1;
        if (pc < NCHUNK)
            gemm_load_chunk(X, W, sb, pc & (GSTAGES - 1), m0, n0, pc * BKH, tid);
        CP_COMMIT();

        const uint32_t abase = sb + (m & (GSTAGES - 1)) * STG_B;
        const uint32_t bbase = abase + TILE_A;
#pragma unroll
        for (int ks = 0; ks < 4; ks++) {
            const int kc = ks * 16;
            uint32_t A[4][4], B[2][4];
#pragma unroll
            for (int f = 0; f < 4; f++) {
                const int r = wm * 64 + f * 16 + lrow + (grp & 1) * 8;
                const int c = kc + (grp >> 1) * 8;
                LDSM4(A[f][0], A[f][1], A[f][2], A[f][3],
                      abase + SW128((uint32_t)(r * 128 + c * 2)));
            }
#pragma unroll
            for (int u = 0; u < 2; u++) {
                const int r = wn * 32 + u * 16 + lrow + (grp >> 1) * 8;
                const int c = kc + (grp & 1) * 8;
                LDSM4(B[u][0], B[u][1], B[u][2], B[u][3],
                      bbase + SW128((uint32_t)(r * 128 + c * 2)));
            }
#pragma unroll
            for (int f = 0; f < 4; f++)
#pragma unroll
                for (int u = 0; u < 2; u++) {
                    MMA_F16(acc[f][2 * u],     A[f][0], A[f][1], A[f][2], A[f][3],
                            B[u][0], B[u][1]);
                    MMA_F16(acc[f][2 * u + 1], A[f][0], A[f][1], A[f][2], A[f][3],
                            B[u][2], B[u][3]);
                }
        }
    }

    if (mode == 1) {
        const int buf = n0 >> 10;
        __half* Yh = (__half*)Yv + (size_t)buf * (NTOK * D_MODEL);
        const int addP = (buf == 0);
#pragma unroll
        for (int f = 0; f < 4; f++) {
            const int r0 = m0 + wm * 64 + f * 16 + lq;
#pragma unroll
            for (int g = 0; g < 4; g++) {
                const int nc = n0 + wn * 32 + g * 8 + 2 * lr;
                const int col = nc & 1023;
                float2 bz = *(const float2*)(bias + nc);
                float2 v0, v1;
                v0.x = acc[f][g][0] + bz.x; v0.y = acc[f][g][1] + bz.y;
                v1.x = acc[f][g][2] + bz.x; v1.y = acc[f][g][3] + bz.y;
                if (addP) {
                    float2 p0 = *(const float2*)(P + (size_t)(r0 & (SEQ - 1)) * D_MODEL + col);
                    float2 p1 = *(const float2*)(P + (size_t)((r0 + 8) & (SEQ - 1)) * D_MODEL + col);
                    v0.x += p0.x; v0.y += p0.y;
                    v1.x += p1.x; v1.y += p1.y;
                }
                *(uint32_t*)(Yh + (size_t)r0 * D_MODEL + col) = pack_half2(v0.x, v0.y);
                *(uint32_t*)(Yh + (size_t)(r0 + 8) * D_MODEL + col) = pack_half2(v1.x, v1.y);
            }
        }
    } else {
        float* Yf = (float*)Yv;
#pragma unroll
        for (int f = 0; f < 4; f++) {
            const int r0 = m0 + wm * 64 + f * 16 + lq;
#pragma unroll
            for (int g = 0; g < 4; g++) {
                const int nc = n0 + wn * 32 + g * 8 + 2 * lr;
                float2 bz = *(const float2*)(bias + nc);
                float2 v0, v1;
                v0.x = acc[f][g][0] + bz.x; v0.y = acc[f][g][1] + bz.y;
                v1.x = acc[f][g][2] + bz.x; v1.y = acc[f][g][3] + bz.y;
                *(float2*)(Yf + (size_t)r0 * D_MODEL + nc) = v0;
                *(float2*)(Yf + (size_t)(r0 + 8) * D_MODEL + nc) = v1;
            }
        }
    }
}

// ============================ fp16 flash attention ==========================
// BQ=128 (8 warps x m16), BJ=128 (softmax fixed cost halved), dk=64.
// Split K/V cp.async groups with staggered waits; PV skips masked j-blocks.
#define BQ 128
#define BJ 128
#define KTILE_B (BJ * 64 * 2)            /* 16384 B per K (or V) stage */
#define AVB_OFF (2 * KTILE_B)
#define ATT_SMEM (4 * KTILE_B)           /* 65536 B */
#define SM_SCALE 0.18033688011112042f    /* 0.125 * log2(e) */

__global__ __launch_bounds__(256, 1) void flash_f16_kernel(
    const __half* __restrict__ Q, const __half* __restrict__ K,
    const __half* __restrict__ V, __half* __restrict__ O)
{
    extern __shared__ char smem[];
    const uint32_t sb = smem_u32(smem);
    const int tid = threadIdx.x;
    const int lane = tid & 31, w = tid >> 5;
    const int lq = lane >> 2, lr = lane & 3;
    const int grp = lane >> 3, lrow = lane & 7;
    const int qt = gridDim.x - 1 - blockIdx.x;   // heavy tiles first
    const int bh = blockIdx.y;
    const int b = bh >> 4, h = bh & 15;
    const int q0 = qt * BQ;
    const size_t base = ((size_t)b * SEQ) * D_MODEL + h * 64;

    uint32_t qa[4][4];
    {
        const __half* q0p = Q + base + (size_t)(q0 + w * 16 + lq) * D_MODEL;
        const __half* q1p = q0p + 8 * D_MODEL;
#pragma unroll
        for (int ks = 0; ks < 4; ks++) {
            const int c = ks * 16 + 2 * lr;
            qa[ks][0] = *(const uint32_t*)(q0p + c);
            qa[ks][1] = *(const uint32_t*)(q1p + c);
            qa[ks][2] = *(const uint32_t*)(q0p + c + 8);
            qa[ks][3] = *(const uint32_t*)(q1p + c + 8);
        }
    }

    float o[8][4];
#pragma unroll
    for (int g = 0; g < 8; g++)
#pragma unroll
        for (int e = 0; e < 4; e++) o[g][e] = 0.f;
    float m0 = -1e30f, m1 = -1e30f, l0 = 0.f, l1 = 0.f;

    const int nj = qt + 1;

#define LOAD_K(t_) do {                                                       \
    const __half* kg = K + base + (size_t)((t_) * BJ) * D_MODEL;              \
    const uint32_t kb = sb + ((t_) & 1) * KTILE_B;                            \
    _Pragma("unroll")                                                         \
    for (int i_ = 0; i_ < 4; i_++) {                                          \
        int seg = tid + (i_ << 8);          /* 0..1023 */                     \
        int row = seg >> 3, c16 = seg & 7;                                    \
        uint32_t off = SW128((uint32_t)(row * 128 + c16 * 16));               \
        CP_ASYNC16(kb + off, kg + (size_t)row * D_MODEL + c16 * 8);           \
    }                                                                         \
} while (0)

#define LOAD_V(t_) do {                                                       \
    const __half* vg = V + base + (size_t)((t_) * BJ) * D_MODEL;              \
    const uint32_t vb = sb + AVB_OFF + ((t_) & 1) * KTILE_B;                  \
    _Pragma("unroll")                                                         \
    for (int i_ = 0; i_ < 4; i_++) {                                          \
        int seg = tid + (i_ << 8);                                            \
        int row = seg >> 3, c16 = seg & 7;                                    \
        uint32_t off = SW128((uint32_t)(row * 128 + c16 * 16));               \
        CP_ASYNC16(vb + off, vg + (size_t)row * D_MODEL + c16 * 8);           \
    }                                                                         \
} while (0)

    LOAD_K(0); CP_COMMIT();
    LOAD_V(0); CP_COMMIT();

    const int qw = q0 + w * 16;
    const int qmax = qw + 15;

    for (int t = 0; t < nj; t++) {
        // wait K(t) (V(t) may still be in flight)
        CP_WAIT(1);
        __syncthreads();
        if (t + 1 < nj) { LOAD_K(t + 1); CP_COMMIT(); }

        const uint32_t kbase = sb + (t & 1) * KTILE_B;
        const uint32_t vbase = sb + AVB_OFF + (t & 1) * KTILE_B;
        const int j0 = t * BJ;

        // ---- S = Q K^T over 128 keys ----
        float s[16][4];
#pragma unroll
        for (int g = 0; g < 16; g++) {
            float init = ((j0 + g * 8) <= qmax) ? 0.f : -1e30f;
            s[g][0] = init; s[g][1] = init; s[g][2] = init; s[g][3] = init;
        }
#pragma unroll
        for (int ks = 0; ks < 4; ks++) {
            const int kc = ks * 16;
#pragma unroll
            for (int u = 0; u < 8; u++) {
                if ((j0 + u * 16) > qmax) continue;
                const int r = u * 16 + lrow + (grp >> 1) * 8;
                const int c = kc + (grp & 1) * 8;
                uint32_t b0, b1, b2, b3;
                LDSM4(b0, b1, b2, b3, kbase + SW128((uint32_t)(r * 128 + c * 2)));
                MMA_F16(s[2 * u],     qa[ks][0], qa[ks][1], qa[ks][2], qa[ks][3], b0, b1);
                MMA_F16(s[2 * u + 1], qa[ks][0], qa[ks][1], qa[ks][2], qa[ks][3], b2, b3);
            }
        }

        // ---- scale into exp2 domain + causal element mask (last tile) ----
#pragma unroll
        for (int g = 0; g < 16; g++) {
            s[g][0] *= SM_SCALE; s[g][1] *= SM_SCALE;
            s[g][2] *= SM_SCALE; s[g][3] *= SM_SCALE;
        }
        if (j0 + BJ - 1 > qw) {
            const int Q0 = qw + lq, Q1 = Q0 + 8;
#pragma unroll
            for (int g = 0; g < 16; g++) {
                const int jc = j0 + g * 8 + 2 * lr;
                if (jc     > Q0) s[g][0] = -1e30f;
                if (jc + 1 > Q0) s[g][1] = -1e30f;
                if (jc     > Q1) s[g][2] = -1e30f;
                if (jc + 1 > Q1) s[g][3] = -1e30f;
            }
        }

        // ---- online softmax (one pass per 128 keys) ----
        float mx0 = -1e30f, mx1 = -1e30f;
#pragma unroll
        for (int g = 0; g < 16; g++) {
            mx0 = fmaxf(mx0, fmaxf(s[g][0], s[g][1]));
            mx1 = fmaxf(mx1, fmaxf(s[g][2], s[g][3]));
        }
        mx0 = fmaxf(mx0, __shfl_xor_sync(0xffffffffu, mx0, 1));
        mx0 = fmaxf(mx0, __shfl_xor_sync(0xffffffffu, mx0, 2));
        mx1 = fmaxf(mx1, __shfl_xor_sync(0xffffffffu, mx1, 1));
        mx1 = fmaxf(mx1, __shfl_xor_sync(0xffffffffu, mx1, 2));
        const float mn0 = fmaxf(m0, mx0), mn1 = fmaxf(m1, mx1);
        const float c0 = ex2(m0 - mn0), c1 = ex2(m1 - mn1);
        m0 = mn0; m1 = mn1;
        float sum0 = 0.f, sum1 = 0.f;
#pragma unroll
        for (int g = 0; g < 16; g++) {
            s[g][0] = ex2(s[g][0] - mn0);
            s[g][1] = ex2(s[g][1] - mn0);
            s[g][2] = ex2(s[g][2] - mn1);
            s[g][3] = ex2(s[g][3] - mn1);
            sum0 += s[g][0] + s[g][1];
            sum1 += s[g][2] + s[g][3];
        }
        sum0 += __shfl_xor_sync(0xffffffffu, sum0, 1);
        sum0 += __shfl_xor_sync(0xffffffffu, sum0, 2);
        sum1 += __shfl_xor_sync(0xffffffffu, sum1, 1);
        sum1 += __shfl_xor_sync(0xffffffffu, sum1, 2);
        l0 = l0 * c0 + sum0;
        l1 = l1 * c1 + sum1;
#pragma unroll
        for (int g = 0; g < 8; g++) {
            o[g][0] *= c0; o[g][1] *= c0;
            o[g][2] *= c1; o[g][3] *= c1;
        }

        // wait V(t); issue V(t+1) after
        if (t + 1 < nj) { CP_WAIT(1); } else { CP_WAIT(0); }
        __syncthreads();
        if (t + 1 < nj) { LOAD_V(t + 1); CP_COMMIT(); }

        // ---- O += P V (pa packed inline per 16-j block; skip masked) ----
#pragma unroll
        for (int kj = 0; kj < 8; kj++) {
            if ((j0 + kj * 16) > qmax) continue;
            uint32_t a0 = pack_half2(s[2 * kj][0],     s[2 * kj][1]);
            uint32_t a1 = pack_half2(s[2 * kj][2],     s[2 * kj][3]);
            uint32_t a2 = pack_half2(s[2 * kj + 1][0], s[2 * kj + 1][1]);
            uint32_t a3 = pack_half2(s[2 * kj + 1][2], s[2 * kj + 1][3]);
#pragma unroll
            for (int u = 0; u < 4; u++) {
                const int r = kj * 16 + lrow + (grp & 1) * 8;
                const int c = u * 16 + (grp >> 1) * 8;
                uint32_t b0, b1, b2, b3;
                LDSM4T(b0, b1, b2, b3, vbase + SW128((uint32_t)(r * 128 + c * 2)));
                MMA_F16(o[2 * u],     a0, a1, a2, a3, b0, b1);
                MMA_F16(o[2 * u + 1], a0, a1, a2, a3, b2, b3);
            }
        }
    }

    const float inv0 = 1.f / l0, inv1 = 1.f / l1;
    __half* o0 = O + base + (size_t)(qw + lq) * D_MODEL;
    __half* o1 = o0 + 8 * D_MODEL;
#pragma unroll
    for (int g = 0; g < 8; g++) {
        const int c = g * 8 + 2 * lr;
        *(uint32_t*)(o0 + c) = pack_half2(o[g][0] * inv0, o[g][1] * inv0);
        *(uint32_t*)(o1 + c) = pack_half2(o[g][2] * inv1, o[g][3] * inv1);
    }
}

// ---------------------------------------------------------------------------
extern "C" void kernel_launch(void* const* d_in, const int* in_sizes, int n_in,
                              void* d_out, int out_size)
{
    const float* x   = (const float*)d_in[0];
    const float* pos = (const float*)d_in[1];
    const float* Wq  = (const float*)d_in[2];
    const float* bq  = (const float*)d_in[3];
    const float* Wk  = (const float*)d_in[4];
    const float* bk  = (const float*)d_in[5];
    const float* Wv  = (const float*)d_in[6];
    const float* bv  = (const float*)d_in[7];
    const float* Wp  = (const float*)d_in[8];
    const float* bp  = (const float*)d_in[9];
    const float* Wo  = (const float*)d_in[10];
    const float* bo  = (const float*)d_in[11];
    float* out = (float*)d_out;

    __half *xh, *posh, *wh, *qkvh, *ctxh;
    float *p, *bqkv;
    cudaGetSymbolAddress((void**)&xh,   g_xh);
    cudaGetSymbolAddress((void**)&posh, g_posh);
    cudaGetSymbolAddress((void**)&wh,   g_wh);
    cudaGetSymbolAddress((void**)&qkvh, g_qkvh);
    cudaGetSymbolAddress((void**)&ctxh, g_ctxh);
    cudaGetSymbolAddress((void**)&p,    g_p);
    cudaGetSymbolAddress((void**)&bqkv, g_bqkv);

    __half* wqkvh = wh;                                  // [3072, 1024]
    __half* woh   = wh + 3 * (size_t)D_MODEL * D_MODEL;
    __half* wph   = wh + 4 * (size_t)D_MODEL * D_MODEL;
    __half* qh = qkvh;
    __half* kh = qkvh + 1 * (size_t)NTOK * D_MODEL;
    __half* vh = qkvh + 2 * (size_t)NTOK * D_MODEL;

    static bool attr_done = false;
    if (!attr_done) {
        cudaFuncSetAttribute(gemm_f16_kernel,
                             cudaFuncAttributeMaxDynamicSharedMemorySize, SM_TOTAL);
        cudaFuncSetAttribute(flash_f16_kernel,
                             cudaFuncAttributeMaxDynamicSharedMemorySize, ATT_SMEM);
        attr_done = true;
    }

    pack_all_kernel<<<2960, 256>>>(x, pos, Wq, Wk, Wv, Wo, Wp, bq, bk, bv,
                                   xh, posh, wh, bqkv);

    dim3 blk(512);
    // p = pos @ Wp^T + bp (fp32): [2048, 1024]
    gemm_f16_kernel<<<dim3(4, 16), blk, SM_TOTAL>>>(posh, wph, bp, nullptr, p, 0);
    // fused QKV: [8192, 3072]
    gemm_f16_kernel<<<dim3(12, 64), blk, SM_TOTAL>>>(xh, wqkvh, bqkv, p, qkvh, 1);
    // attention -> ctx (fp16)
    flash_f16_kernel<<<dim3(SEQ / BQ, BATCH * 16), 256, ATT_SMEM>>>(qh, kh, vh, ctxh);
    // out = ctx @ Wo^T + bo (fp32): [8192, 1024]
    gemm_f16_kernel<<<dim3(4, 64), blk, SM_TOTAL>>>(ctxh, woh, bo, nullptr, out, 0);
}

// round 12
// speedup vs baseline: 1.5651x; 1.0004x over previous
#include <cuda_runtime.h>
#include <cuda_fp16.h>
#include <cstdint>
#include <math.h>

#define D_MODEL 1024
#define SEQ     2048
#define BATCH   4
#define NTOK    (BATCH * SEQ)   /* 8192 */

// ---------------- scratch (device globals; no allocations allowed) ----------
__device__ __half g_xh[NTOK * D_MODEL];
__device__ __half g_posh[SEQ * D_MODEL];
__device__ __half g_wh[5][D_MODEL * D_MODEL];   // Wq,Wk,Wv,Wo,Wp (fp16)
__device__ __half g_qkvh[3 * NTOK * D_MODEL];   // q, k, v contiguous
__device__ __half g_ctxh[NTOK * D_MODEL];
__device__ float  g_p[SEQ * D_MODEL];           // pos projection (fp32)
__device__ float  g_bqkv[3 * D_MODEL];          // bq|bk|bv concatenated

// ============================ helpers =======================================
#define CP_ASYNC16(dst, src) \
    asm volatile("cp.async.cg.shared.global [%0], [%1], 16;" \
                 :: "r"(dst), "l"(src) : "memory")
#define CP_COMMIT() asm volatile("cp.async.commit_group;" ::: "memory")
#define CP_WAIT(n)  asm volatile("cp.async.wait_group %0;" :: "n"(n) : "memory")

#define SW128(off) ((off) ^ (((off) >> 3) & 0x70))

__device__ __forceinline__ uint32_t smem_u32(const void* p) {
    uint32_t a;
    asm("{ .reg .u64 t; cvta.to.shared.u64 t, %1; cvt.u32.u64 %0, t; }"
        : "=r"(a) : "l"(p));
    return a;
}

__device__ __forceinline__ uint32_t pack_half2(float a, float b) {
    __half2 h = __floats2half2_rn(a, b);
    return *(uint32_t*)&h;
}

__device__ __forceinline__ float ex2(float x) {
    float y;
    asm("ex2.approx.ftz.f32 %0, %1;" : "=f"(y) : "f"(x));
    return y;
}

__device__ __forceinline__ uint32_t ex2_h2(uint32_t x) {
    uint32_t y;
    asm("ex2.approx.f16x2 %0, %1;" : "=r"(y) : "r"(x));
    return y;
}

#define LDSM4(r0, r1, r2, r3, addr) \
    asm volatile("ldmatrix.sync.aligned.m8n8.x4.shared.b16 {%0,%1,%2,%3}, [%4];" \
                 : "=r"(r0), "=r"(r1), "=r"(r2), "=r"(r3) : "r"(addr))

#define LDSM4T(r0, r1, r2, r3, addr) \
    asm volatile("ldmatrix.sync.aligned.m8n8.x4.trans.shared.b16 {%0,%1,%2,%3}, [%4];" \
                 : "=r"(r0), "=r"(r1), "=r"(r2), "=r"(r3) : "r"(addr))

#define MMA_F16(c, a0, a1, a2, a3, b0, b1) \
    asm volatile( \
        "mma.sync.aligned.m16n8k16.row.col.f32.f16.f16.f32 " \
        "{%0,%1,%2,%3}, {%4,%5,%6,%7}, {%8,%9}, {%0,%1,%2,%3};" \
        : "+f"((c)[0]), "+f"((c)[1]), "+f"((c)[2]), "+f"((c)[3]) \
        : "r"(a0), "r"(a1), "r"(a2), "r"(a3), "r"(b0), "r"(b1))

// ---------------- fused pack: x, pos, 5 weights -> fp16; bq|bk|bv -> fp32 ---
#define N4_X   (NTOK * D_MODEL / 4)
#define N4_POS (SEQ * D_MODEL / 4)
#define N4_W   (D_MODEL * D_MODEL / 4)
#define N4_TOT (N4_X + N4_POS + 5 * N4_W)

__global__ __launch_bounds__(256) void pack_all_kernel(
    const float* __restrict__ x, const float* __restrict__ pos,
    const float* __restrict__ Wq, const float* __restrict__ Wk,
    const float* __restrict__ Wv, const float* __restrict__ Wo,
    const float* __restrict__ Wp,
    const float* __restrict__ bq, const float* __restrict__ bk,
    const float* __restrict__ bv,
    __half* __restrict__ xh, __half* __restrict__ posh,
    __half* __restrict__ wh, float* __restrict__ bqkv)
{
    int i = blockIdx.x * blockDim.x + threadIdx.x;
    const int stride = gridDim.x * blockDim.x;

    if (i < 3 * D_MODEL / 4) {
        const float* src = (i < 256) ? bq : (i < 512) ? bk : bv;
        ((float4*)bqkv)[i] = ((const float4*)src)[i & 255];
    }

    for (; i < N4_TOT; i += stride) {
        const float* s;
        __half* d;
        int idx;
        if (i < N4_X) {
            s = x; d = xh; idx = i;
        } else if (i < N4_X + N4_POS) {
            s = pos; d = posh; idx = i - N4_X;
        } else {
            int wi = i - N4_X - N4_POS;
            int wsel = wi / N4_W;
            idx = wi - wsel * N4_W;
            s = (wsel == 0) ? Wq : (wsel == 1) ? Wk : (wsel == 2) ? Wv
                : (wsel == 3) ? Wo : Wp;
            d = wh + (size_t)wsel * (D_MODEL * D_MODEL);
        }
        float4 t = ((const float4*)s)[idx];
        uint2 r;
        r.x = pack_half2(t.x, t.y);
        r.y = pack_half2(t.z, t.w);
        ((uint2*)d)[idx] = r;
    }
}

// ============================ fp16 mma GEMM =================================
// Tile 128x256x64(half), 512 threads (16 warps, 2 M x 8 N), warp tile 64x32.
#define BM 128
#define BN 256
#define BKH 64
#define GSTAGES 4
#define NCHUNK (D_MODEL / BKH)          /* 16 */
#define TILE_A (BM * BKH * 2)           /* 16384 B */
#define TILE_BB (BN * BKH * 2)          /* 32768 B */
#define STG_B  (TILE_A + TILE_BB)       /* 49152 B */
#define SM_TOTAL (GSTAGES * STG_B)      /* 196608 B */

__device__ __forceinline__ void gemm_load_chunk(
    const __half* __restrict__ X, const __half* __restrict__ W,
    uint32_t sbase, int stage, int m0, int n0, int kof, int tid)
{
    const uint32_t abase = sbase + stage * STG_B;
    const uint32_t bbase = abase + TILE_A;
#pragma unroll
    for (int i = 0; i < 2; i++) {
        int seg = tid + (i << 9);
        int row = seg >> 3, c16 = seg & 7;
        uint32_t off = row * 128 + c16 * 16;
        CP_ASYNC16(abase + SW128(off),
                   X + (size_t)(m0 + row) * D_MODEL + kof + c16 * 8);
    }
#pragma unroll
    for (int i = 0; i < 4; i++) {
        int seg = tid + (i << 9);
        int row = seg >> 3, c16 = seg & 7;
        uint32_t off = row * 128 + c16 * 16;
        CP_ASYNC16(bbase + SW128(off),
                   W + (size_t)(n0 + row) * D_MODEL + kof + c16 * 8);
    }
}

__global__ __launch_bounds__(512, 1) void gemm_f16_kernel(
    const __half* __restrict__ X, const __half* __restrict__ W,
    const float* __restrict__ bias, const float* __restrict__ P,
    void* __restrict__ Yv, int mode)
{
    extern __shared__ char smem[];
    const uint32_t sb = smem_u32(smem);
    const int tid = threadIdx.x;
    const int lane = tid & 31, wid = tid >> 5;
    const int wm = wid >> 3;          // 0..1
    const int wn = wid & 7;           // 0..7
    const int grp = lane >> 3, lrow = lane & 7;
    const int lq = lane >> 2, lr = lane & 3;
    const int n0 = blockIdx.x * BN;
    const int m0 = blockIdx.y * BM;

    float acc[4][4][4];
#pragma unroll
    for (int f = 0; f < 4; f++)
#pragma unroll
        for (int g = 0; g < 4; g++)
#pragma unroll
            for (int e = 0; e < 4; e++) acc[f][g][e] = 0.f;

#pragma unroll
    for (int c = 0; c < GSTAGES - 1; c++) {
        gemm_load_chunk(X, W, sb, c, m0, n0, c * BKH, tid);
        CP_COMMIT();
    }

    for (int m = 0; m < NCHUNK; m++) {
        CP_WAIT(GSTAGES - 2);
        __syncthreads();

        const int pc = m + GSTAGES - 1;
        if (pc < NCHUNK)
            gemm_load_chunk(X, W, sb, pc & (GSTAGES - 1), m0, n0, pc * BKH, tid);
        CP_COMMIT();

        const uint32_t abase = sb + (m & (GSTAGES - 1)) * STG_B;
        const uint32_t bbase = abase + TILE_A;
#pragma unroll
        for (int ks = 0; ks < 4; ks++) {
            const int kc = ks * 16;
            uint32_t A[4][4], B[2][4];
#pragma unroll
            for (int f = 0; f < 4; f++) {
                const int r = wm * 64 + f * 16 + lrow + (grp & 1) * 8;
                const int c = kc + (grp >> 1) * 8;
                LDSM4(A[f][0], A[f][1], A[f][2], A[f][3],
                      abase + SW128((uint32_t)(r * 128 + c * 2)));
            }
#pragma unroll
            for (int u = 0; u < 2; u++) {
                const int r = wn * 32 + u * 16 + lrow + (grp >> 1) * 8;
                const int c = kc + (grp & 1) * 8;
                LDSM4(B[u][0], B[u][1], B[u][2], B[u][3],
                      bbase + SW128((uint32_t)(r * 128 + c * 2)));
            }
#pragma unroll
            for (int f = 0; f < 4; f++)
#pragma unroll
                for (int u = 0; u < 2; u++) {
                    MMA_F16(acc[f][2 * u],     A[f][0], A[f][1], A[f][2], A[f][3],
                            B[u][0], B[u][1]);
                    MMA_F16(acc[f][2 * u + 1], A[f][0], A[f][1], A[f][2], A[f][3],
                            B[u][2], B[u][3]);
                }
        }
    }

    if (mode == 1) {
        const int buf = n0 >> 10;
        __half* Yh = (__half*)Yv + (size_t)buf * (NTOK * D_MODEL);
        const int addP = (buf == 0);
#pragma unroll
        for (int f = 0; f < 4; f++) {
            const int r0 = m0 + wm * 64 + f * 16 + lq;
#pragma unroll
            for (int g = 0; g < 4; g++) {
                const int nc = n0 + wn * 32 + g * 8 + 2 * lr;
                const int col = nc & 1023;
                float2 bz = *(const float2*)(bias + nc);
                float2 v0, v1;
                v0.x = acc[f][g][0] + bz.x; v0.y = acc[f][g][1] + bz.y;
                v1.x = acc[f][g][2] + bz.x; v1.y = acc[f][g][3] + bz.y;
                if (addP) {
                    float2 p0 = *(const float2*)(P + (size_t)(r0 & (SEQ - 1)) * D_MODEL + col);
                    float2 p1 = *(const float2*)(P + (size_t)((r0 + 8) & (SEQ - 1)) * D_MODEL + col);
                    v0.x += p0.x; v0.y += p0.y;
                    v1.x += p1.x; v1.y += p1.y;
                }
                *(uint32_t*)(Yh + (size_t)r0 * D_MODEL + col) = pack_half2(v0.x, v0.y);
                *(uint32_t*)(Yh + (size_t)(r0 + 8) * D_MODEL + col) = pack_half2(v1.x, v1.y);
            }
        }
    } else {
        float* Yf = (float*)Yv;
#pragma unroll
        for (int f = 0; f < 4; f++) {
            const int r0 = m0 + wm * 64 + f * 16 + lq;
#pragma unroll
            for (int g = 0; g < 4; g++) {
                const int nc = n0 + wn * 32 + g * 8 + 2 * lr;
                float2 bz = *(const float2*)(bias + nc);
                float2 v0, v1;
                v0.x = acc[f][g][0] + bz.x; v0.y = acc[f][g][1] + bz.y;
                v1.x = acc[f][g][2] + bz.x; v1.y = acc[f][g][3] + bz.y;
                *(float2*)(Yf + (size_t)r0 * D_MODEL + nc) = v0;
                *(float2*)(Yf + (size_t)(r0 + 8) * D_MODEL + nc) = v1;
            }
        }
    }
}

// ============================ fp16 flash attention ==========================
// BQ=128 (8 warps x m16), BJ=128, dk=64. Softmax: f16x2 ex2 (p produced
// directly as packed PV A-fragments) + row sums via ones-B MMA (no shuffles).
#define BQ 128
#define BJ 128
#define KTILE_B (BJ * 64 * 2)            /* 16384 B per K (or V) stage */
#define AVB_OFF (2 * KTILE_B)
#define ATT_SMEM (4 * KTILE_B)           /* 65536 B */
#define SM_SCALE 0.18033688011112042f    /* 0.125 * log2(e) */
#define ONES_H2 0x3C003C00u              /* half2(1.0, 1.0) */

__global__ __launch_bounds__(256, 1) void flash_f16_kernel(
    const __half* __restrict__ Q, const __half* __restrict__ K,
    const __half* __restrict__ V, __half* __restrict__ O)
{
    extern __shared__ char smem[];
    const uint32_t sb = smem_u32(smem);
    const int tid = threadIdx.x;
    const int lane = tid & 31, w = tid >> 5;
    const int lq = lane >> 2, lr = lane & 3;
    const int grp = lane >> 3, lrow = lane & 7;
    const int qt = gridDim.x - 1 - blockIdx.x;   // heavy tiles first
    const int bh = blockIdx.y;
    const int b = bh >> 4, h = bh & 15;
    const int q0 = qt * BQ;
    const size_t base = ((size_t)b * SEQ) * D_MODEL + h * 64;

    uint32_t qa[4][4];
    {
        const __half* q0p = Q + base + (size_t)(q0 + w * 16 + lq) * D_MODEL;
        const __half* q1p = q0p + 8 * D_MODEL;
#pragma unroll
        for (int ks = 0; ks < 4; ks++) {
            const int c = ks * 16 + 2 * lr;
            qa[ks][0] = *(const uint32_t*)(q0p + c);
            qa[ks][1] = *(const uint32_t*)(q1p + c);
            qa[ks][2] = *(const uint32_t*)(q0p + c + 8);
            qa[ks][3] = *(const uint32_t*)(q1p + c + 8);
        }
    }

    float o[8][4];
#pragma unroll
    for (int g = 0; g < 8; g++)
#pragma unroll
        for (int e = 0; e < 4; e++) o[g][e] = 0.f;
    float m0 = -1e30f, m1 = -1e30f, l0 = 0.f, l1 = 0.f;

    const int nj = qt + 1;

#define LOAD_K(t_) do {                                                       \
    const __half* kg = K + base + (size_t)((t_) * BJ) * D_MODEL;              \
    const uint32_t kb = sb + ((t_) & 1) * KTILE_B;                            \
    _Pragma("unroll")                                                         \
    for (int i_ = 0; i_ < 4; i_++) {                                          \
        int seg = tid + (i_ << 8);          /* 0..1023 */                     \
        int row = seg >> 3, c16 = seg & 7;                                    \
        uint32_t off = SW128((uint32_t)(row * 128 + c16 * 16));               \
        CP_ASYNC16(kb + off, kg + (size_t)row * D_MODEL + c16 * 8);           \
    }                                                                         \
} while (0)

#define LOAD_V(t_) do {                                                       \
    const __half* vg = V + base + (size_t)((t_) * BJ) * D_MODEL;              \
    const uint32_t vb = sb + AVB_OFF + ((t_) & 1) * KTILE_B;                  \
    _Pragma("unroll")                                                         \
    for (int i_ = 0; i_ < 4; i_++) {                                          \
        int seg = tid + (i_ << 8);                                            \
        int row = seg >> 3, c16 = seg & 7;                                    \
        uint32_t off = SW128((uint32_t)(row * 128 + c16 * 16));               \
        CP_ASYNC16(vb + off, vg + (size_t)row * D_MODEL + c16 * 8);           \
    }                                                                         \
} while (0)

    LOAD_K(0); CP_COMMIT();
    LOAD_V(0); CP_COMMIT();

    const int qw = q0 + w * 16;
    const int qmax = qw + 15;

    for (int t = 0; t < nj; t++) {
        // wait K(t) (V(t) may still be in flight)
        CP_WAIT(1);
        __syncthreads();
        if (t + 1 < nj) { LOAD_K(t + 1); CP_COMMIT(); }

        const uint32_t kbase = sb + (t & 1) * KTILE_B;
        const uint32_t vbase = sb + AVB_OFF + (t & 1) * KTILE_B;
        const int j0 = t * BJ;

        // ---- S = Q K^T over 128 keys ----
        float s[16][4];
#pragma unroll
        for (int g = 0; g < 16; g++) {
            float init = ((j0 + g * 8) <= qmax) ? 0.f : -1e30f;
            s[g][0] = init; s[g][1] = init; s[g][2] = init; s[g][3] = init;
        }
#pragma unroll
        for (int ks = 0; ks < 4; ks++) {
            const int kc = ks * 16;
#pragma unroll
            for (int u = 0; u < 8; u++) {
                if ((j0 + u * 16) > qmax) continue;
                const int r = u * 16 + lrow + (grp >> 1) * 8;
                const int c = kc + (grp & 1) * 8;
                uint32_t b0, b1, b2, b3;
                LDSM4(b0, b1, b2, b3, kbase + SW128((uint32_t)(r * 128 + c * 2)));
                MMA_F16(s[2 * u],     qa[ks][0], qa[ks][1], qa[ks][2], qa[ks][3], b0, b1);
                MMA_F16(s[2 * u + 1], qa[ks][0], qa[ks][1], qa[ks][2], qa[ks][3], b2, b3);
            }
        }

        // ---- scale into exp2 domain + causal element mask (diag tiles) ----
#pragma unroll
        for (int g = 0; g < 16; g++) {
            s[g][0] *= SM_SCALE; s[g][1] *= SM_SCALE;
            s[g][2] *= SM_SCALE; s[g][3] *= SM_SCALE;
        }
        if (j0 + BJ - 1 > qw) {
            const int Q0 = qw + lq, Q1 = Q0 + 8;
#pragma unroll
            for (int g = 0; g < 16; g++) {
                const int jc = j0 + g * 8 + 2 * lr;
                if (jc     > Q0) s[g][0] = -1e30f;
                if (jc + 1 > Q0) s[g][1] = -1e30f;
                if (jc     > Q1) s[g][2] = -1e30f;
                if (jc + 1 > Q1) s[g][3] = -1e30f;
            }
        }

        // ---- row max (only remaining shuffle reduction) ----
        float mx0 = -1e30f, mx1 = -1e30f;
#pragma unroll
        for (int g = 0; g < 16; g++) {
            mx0 = fmaxf(mx0, fmaxf(s[g][0], s[g][1]));
            mx1 = fmaxf(mx1, fmaxf(s[g][2], s[g][3]));
        }
        mx0 = fmaxf(mx0, __shfl_xor_sync(0xffffffffu, mx0, 1));
        mx0 = fmaxf(mx0, __shfl_xor_sync(0xffffffffu, mx0, 2));
        mx1 = fmaxf(mx1, __shfl_xor_sync(0xffffffffu, mx1, 1));
        mx1 = fmaxf(mx1, __shfl_xor_sync(0xffffffffu, mx1, 2));
        const float mn0 = fmaxf(m0, mx0), mn1 = fmaxf(m1, mx1);
        const float c0 = ex2(m0 - mn0), c1 = ex2(m1 - mn1);
        m0 = mn0; m1 = mn1;

        // ---- p = exp2(s - mn) via f16x2 ex2 (results ARE PV A-fragments) --
        uint32_t pg0[16], pg1[16];
#pragma unroll
        for (int g = 0; g < 16; g++) {
            pg0[g] = ex2_h2(pack_half2(s[g][0] - mn0, s[g][1] - mn0));
            pg1[g] = ex2_h2(pack_half2(s[g][2] - mn1, s[g][3] - mn1));
        }

        // ---- row sums via ones-B MMA (exact fp32, no shuffles) ----
        float ls[4] = {0.f, 0.f, 0.f, 0.f};
#pragma unroll
        for (int kj = 0; kj < 8; kj++) {
            if ((j0 + kj * 16) > qmax) continue;
            MMA_F16(ls, pg0[2 * kj], pg1[2 * kj],
                    pg0[2 * kj + 1], pg1[2 * kj + 1], ONES_H2, ONES_H2);
        }
        l0 = l0 * c0 + ls[0];
        l1 = l1 * c1 + ls[2];
#pragma unroll
        for (int g = 0; g < 8; g++) {
            o[g][0] *= c0; o[g][1] *= c0;
            o[g][2] *= c1; o[g][3] *= c1;
        }

        // wait V(t); issue V(t+1) after
        if (t + 1 < nj) { CP_WAIT(1); } else { CP_WAIT(0); }
        __syncthreads();
        if (t + 1 < nj) { LOAD_V(t + 1); CP_COMMIT(); }

        // ---- O += P V (A-fragments already packed; skip masked blocks) ----
#pragma unroll
        for (int kj = 0; kj < 8; kj++) {
            if ((j0 + kj * 16) > qmax) continue;
            const uint32_t a0 = pg0[2 * kj],     a1 = pg1[2 * kj];
            const uint32_t a2 = pg0[2 * kj + 1], a3 = pg1[2 * kj + 1];
#pragma unroll
            for (int u = 0; u < 4; u++) {
                const int r = kj * 16 + lrow + (grp & 1) * 8;
                const int c = u * 16 + (grp >> 1) * 8;
                uint32_t b0, b1, b2, b3;
                LDSM4T(b0, b1, b2, b3, vbase + SW128((uint32_t)(r * 128 + c * 2)));
                MMA_F16(o[2 * u],     a0, a1, a2, a3, b0, b1);
                MMA_F16(o[2 * u + 1], a0, a1, a2, a3, b2, b3);
            }
        }
    }

    const float inv0 = 1.f / l0, inv1 = 1.f / l1;
    __half* o0 = O + base + (size_t)(qw + lq) * D_MODEL;
    __half* o1 = o0 + 8 * D_MODEL;
#pragma unroll
    for (int g = 0; g < 8; g++) {
        const int c = g * 8 + 2 * lr;
        *(uint32_t*)(o0 + c) = pack_half2(o[g][0] * inv0, o[g][1] * inv0);
        *(uint32_t*)(o1 + c) = pack_half2(o[g][2] * inv1, o[g][3] * inv1);
    }
}

// ---------------------------------------------------------------------------
extern "C" void kernel_launch(void* const* d_in, const int* in_sizes, int n_in,
                              void* d_out, int out_size)
{
    const float* x   = (const float*)d_in[0];
    const float* pos = (const float*)d_in[1];
    const float* Wq  = (const float*)d_in[2];
    const float* bq  = (const float*)d_in[3];
    const float* Wk  = (const float*)d_in[4];
    const float* bk  = (const float*)d_in[5];
    const float* Wv  = (const float*)d_in[6];
    const float* bv  = (const float*)d_in[7];
    const float* Wp  = (const float*)d_in[8];
    const float* bp  = (const float*)d_in[9];
    const float* Wo  = (const float*)d_in[10];
    const float* bo  = (const float*)d_in[11];
    float* out = (float*)d_out;

    __half *xh, *posh, *wh, *qkvh, *ctxh;
    float *p, *bqkv;
    cudaGetSymbolAddress((void**)&xh,   g_xh);
    cudaGetSymbolAddress((void**)&posh, g_posh);
    cudaGetSymbolAddress((void**)&wh,   g_wh);
    cudaGetSymbolAddress((void**)&qkvh, g_qkvh);
    cudaGetSymbolAddress((void**)&ctxh, g_ctxh);
    cudaGetSymbolAddress((void**)&p,    g_p);
    cudaGetSymbolAddress((void**)&bqkv, g_bqkv);

    __half* wqkvh = wh;                                  // [3072, 1024]
    __half* woh   = wh + 3 * (size_t)D_MODEL * D_MODEL;
    __half* wph   = wh + 4 * (size_t)D_MODEL * D_MODEL;
    __half* qh = qkvh;
    __half* kh = qkvh + 1 * (size_t)NTOK * D_MODEL;
    __half* vh = qkvh + 2 * (size_t)NTOK * D_MODEL;

    static bool attr_done = false;
    if (!attr_done) {
        cudaFuncSetAttribute(gemm_f16_kernel,
                             cudaFuncAttributeMaxDynamicSharedMemorySize, SM_TOTAL);
        cudaFuncSetAttribute(flash_f16_kernel,
                             cudaFuncAttributeMaxDynamicSharedMemorySize, ATT_SMEM);
        attr_done = true;
    }

    pack_all_kernel<<<2960, 256>>>(x, pos, Wq, Wk, Wv, Wo, Wp, bq, bk, bv,
                                   xh, posh, wh, bqkv);

    dim3 blk(512);
    // p = pos @ Wp^T + bp (fp32): [2048, 1024]
    gemm_f16_kernel<<<dim3(4, 16), blk, SM_TOTAL>>>(posh, wph, bp, nullptr, p, 0);
    // fused QKV: [8192, 3072]
    gemm_f16_kernel<<<dim3(12, 64), blk, SM_TOTAL>>>(xh, wqkvh, bqkv, p, qkvh, 1);
    // attention -> ctx (fp16)
    flash_f16_kernel<<<dim3(SEQ / BQ, BATCH * 16), 256, ATT_SMEM>>>(qh, kh, vh, ctxh);
    // out = ctx @ Wo^T + bo (fp32): [8192, 1024]
    gemm_f16_kernel<<<dim3(4, 64), blk, SM_TOTAL>>>(ctxh, woh, bo, nullptr, out, 0);
}

// round 13
// speedup vs baseline: 1.6353x; 1.0449x over previous
#include <cuda_runtime.h>
#include <cuda_fp16.h>
#include <cstdint>
#include <math.h>

#define D_MODEL 1024
#define SEQ     2048
#define BATCH   4
#define NTOK    (BATCH * SEQ)   /* 8192 */

// ---------------- scratch (device globals; no allocations allowed) ----------
__device__ __half g_xh[NTOK * D_MODEL];
__device__ __half g_posh[SEQ * D_MODEL];
__device__ __half g_wh[5][D_MODEL * D_MODEL];   // Wq,Wk,Wv,Wo,Wp (fp16)
__device__ __half g_qkvh[3 * NTOK * D_MODEL];   // q, k, v contiguous
__device__ __half g_ctxh[NTOK * D_MODEL];
__device__ __half g_ph[SEQ * D_MODEL];          // pos projection (fp16)
__device__ float  g_bqkv[3 * D_MODEL];          // bq|bk|bv concatenated

// ============================ helpers =======================================
#define CP_ASYNC16(dst, src) \
    asm volatile("cp.async.cg.shared.global [%0], [%1], 16;" \
                 :: "r"(dst), "l"(src) : "memory")
#define CP_COMMIT() asm volatile("cp.async.commit_group;" ::: "memory")
#define CP_WAIT(n)  asm volatile("cp.async.wait_group %0;" :: "n"(n) : "memory")

#define SW128(off) ((off) ^ (((off) >> 3) & 0x70))

__device__ __forceinline__ uint32_t smem_u32(const void* p) {
    uint32_t a;
    asm("{ .reg .u64 t; cvta.to.shared.u64 t, %1; cvt.u32.u64 %0, t; }"
        : "=r"(a) : "l"(p));
    return a;
}

__device__ __forceinline__ uint32_t pack_half2(float a, float b) {
    __half2 h = __floats2half2_rn(a, b);
    return *(uint32_t*)&h;
}

__device__ __forceinline__ float ex2(float x) {
    float y;
    asm("ex2.approx.ftz.f32 %0, %1;" : "=f"(y) : "f"(x));
    return y;
}

__device__ __forceinline__ uint32_t ex2_h2(uint32_t x) {
    uint32_t y;
    asm("ex2.approx.f16x2 %0, %1;" : "=r"(y) : "r"(x));
    return y;
}

// add two packed half2 in fp32 domain, return packed half2
__device__ __forceinline__ uint32_t hadd2_f32(uint32_t a, uint32_t b) {
    __half2 ha = *(__half2*)&a, hb = *(__half2*)&b;
    float2 fa = __half22float2(ha), fb = __half22float2(hb);
    return pack_half2(fa.x + fb.x, fa.y + fb.y);
}

#define LDSM4(r0, r1, r2, r3, addr) \
    asm volatile("ldmatrix.sync.aligned.m8n8.x4.shared.b16 {%0,%1,%2,%3}, [%4];" \
                 : "=r"(r0), "=r"(r1), "=r"(r2), "=r"(r3) : "r"(addr))

#define LDSM4T(r0, r1, r2, r3, addr) \
    asm volatile("ldmatrix.sync.aligned.m8n8.x4.trans.shared.b16 {%0,%1,%2,%3}, [%4];" \
                 : "=r"(r0), "=r"(r1), "=r"(r2), "=r"(r3) : "r"(addr))

#define MMA_F16(c, a0, a1, a2, a3, b0, b1) \
    asm volatile( \
        "mma.sync.aligned.m16n8k16.row.col.f32.f16.f16.f32 " \
        "{%0,%1,%2,%3}, {%4,%5,%6,%7}, {%8,%9}, {%0,%1,%2,%3};" \
        : "+f"((c)[0]), "+f"((c)[1]), "+f"((c)[2]), "+f"((c)[3]) \
        : "r"(a0), "r"(a1), "r"(a2), "r"(a3), "r"(b0), "r"(b1))

// ---------------- fused pack: exact-cover grid (1 float4 per thread) --------
#define N4_X   (NTOK * D_MODEL / 4)      /* 2097152 */
#define N4_POS (SEQ * D_MODEL / 4)       /*  524288 */
#define N4_W   (D_MODEL * D_MODEL / 4)   /*  262144 */
#define N4_TOT (N4_X + N4_POS + 5 * N4_W)   /* 3932160 = 15360 * 256 */

__global__ __launch_bounds__(256) void pack_all_kernel(
    const float* __restrict__ x, const float* __restrict__ pos,
    const float* __restrict__ Wq, const float* __restrict__ Wk,
    const float* __restrict__ Wv, const float* __restrict__ Wo,
    const float* __restrict__ Wp,
    const float* __restrict__ bq, const float* __restrict__ bk,
    const float* __restrict__ bv,
    __half* __restrict__ xh, __half* __restrict__ posh,
    __half* __restrict__ wh, float* __restrict__ bqkv)
{
    const int i = blockIdx.x * blockDim.x + threadIdx.x;

    if (i < 3 * D_MODEL / 4) {
        const float* src = (i < 256) ? bq : (i < 512) ? bk : bv;
        ((float4*)bqkv)[i] = ((const float4*)src)[i & 255];
    }

    const float* s;
    __half* d;
    int idx;
    if (i < N4_X) {
        s = x; d = xh; idx = i;
    } else if (i < N4_X + N4_POS) {
        s = pos; d = posh; idx = i - N4_X;
    } else {
        int wi = i - N4_X - N4_POS;
        const float* ws[5] = {Wq, Wk, Wv, Wo, Wp};
        int wsel = (wi >= 4 * N4_W) ? 4 : (wi >> 18);   /* N4_W = 2^18 */
        idx = wi - wsel * N4_W;
        s = ws[wsel];
        d = wh + (size_t)wsel * (D_MODEL * D_MODEL);
    }
    float4 t = ((const float4*)s)[idx];
    uint2 r;
    r.x = pack_half2(t.x, t.y);
    r.y = pack_half2(t.z, t.w);
    ((uint2*)d)[idx] = r;
}

// ============================ fp16 mma GEMM =================================
// Tile 128x256x64(half), 512 threads (16 warps, 2 M x 8 N), warp tile 64x32.
// mode 0: Wo GEMM, fp32 out. mode 1: merged QKV (bx<12) + pos (bx==12),
// both fp16 out; q no longer adds p (done in flash).
#define BM 128
#define BN 256
#define BKH 64
#define GSTAGES 4
#define NCHUNK (D_MODEL / BKH)          /* 16 */
#define TILE_A (BM * BKH * 2)           /* 16384 B */
#define TILE_BB (BN * BKH * 2)          /* 32768 B */
#define STG_B  (TILE_A + TILE_BB)       /* 49152 B */
#define SM_TOTAL (GSTAGES * STG_B)      /* 196608 B */

__device__ __forceinline__ void gemm_load_chunk(
    const __half* __restrict__ X, const __half* __restrict__ W,
    uint32_t sbase, int stage, int m0, int n0, int kof, int tid)
{
    const uint32_t abase = sbase + stage * STG_B;
    const uint32_t bbase = abase + TILE_A;
#pragma unroll
    for (int i = 0; i < 2; i++) {
        int seg = tid + (i << 9);
        int row = seg >> 3, c16 = seg & 7;
        uint32_t off = row * 128 + c16 * 16;
        CP_ASYNC16(abase + SW128(off),
                   X + (size_t)(m0 + row) * D_MODEL + kof + c16 * 8);
    }
#pragma unroll
    for (int i = 0; i < 4; i++) {
        int seg = tid + (i << 9);
        int row = seg >> 3, c16 = seg & 7;
        uint32_t off = row * 128 + c16 * 16;
        CP_ASYNC16(bbase + SW128(off),
                   W + (size_t)(n0 + row) * D_MODEL + kof + c16 * 8);
    }
}

__global__ __launch_bounds__(512, 1) void gemm_f16_kernel(
    const __half* __restrict__ X0, const __half* __restrict__ W0,
    const float* __restrict__ bias0, void* __restrict__ Y0, int mode,
    const __half* __restrict__ Xp, const __half* __restrict__ Wpp,
    const float* __restrict__ biasp, __half* __restrict__ Yp)
{
    extern __shared__ char smem[];
    const uint32_t sb = smem_u32(smem);
    const int tid = threadIdx.x;
    const int lane = tid & 31, wid = tid >> 5;
    const int wm = wid >> 3;          // 0..1
    const int wn = wid & 7;           // 0..7
    const int grp = lane >> 3, lrow = lane & 7;
    const int lq = lane >> 2, lr = lane & 3;

    const bool isPos = (mode == 1) && (blockIdx.x == 12);
    const __half* X;
    const __half* W;
    const float* bias;
    int m0, n0;
    if (isPos) {
        X = Xp; W = Wpp; bias = biasp;
        n0 = (blockIdx.y >> 4) * BN;
        m0 = (blockIdx.y & 15) * BM;
    } else {
        X = X0; W = W0; bias = bias0;
        n0 = blockIdx.x * BN;
        m0 = blockIdx.y * BM;
    }

    float acc[4][4][4];
#pragma unroll
    for (int f = 0; f < 4; f++)
#pragma unroll
        for (int g = 0; g < 4; g++)
#pragma unroll
            for (int e = 0; e < 4; e++) acc[f][g][e] = 0.f;

#pragma unroll
    for (int c = 0; c < GSTAGES - 1; c++) {
        gemm_load_chunk(X, W, sb, c, m0, n0, c * BKH, tid);
        CP_COMMIT();
    }

    for (int m = 0; m < NCHUNK; m++) {
        CP_WAIT(GSTAGES - 2);
        __syncthreads();

        const int pc = m + GSTAGES - 1;
        if (pc < NCHUNK)
            gemm_load_chunk(X, W, sb, pc & (GSTAGES - 1), m0, n0, pc * BKH, tid);
        CP_COMMIT();

        const uint32_t abase = sb + (m & (GSTAGES - 1)) * STG_B;
        const uint32_t bbase = abase + TILE_A;
#pragma unroll
        for (int ks = 0; ks < 4; ks++) {
            const int kc = ks * 16;
            uint32_t A[4][4], B[2][4];
#pragma unroll
            for (int f = 0; f < 4; f++) {
                const int r = wm * 64 + f * 16 + lrow + (grp & 1) * 8;
                const int c = kc + (grp >> 1) * 8;
                LDSM4(A[f][0], A[f][1], A[f][2], A[f][3],
                      abase + SW128((uint32_t)(r * 128 + c * 2)));
            }
#pragma unroll
            for (int u = 0; u < 2; u++) {
                const int r = wn * 32 + u * 16 + lrow + (grp >> 1) * 8;
                const int c = kc + (grp & 1) * 8;
                LDSM4(B[u][0], B[u][1], B[u][2], B[u][3],
                      bbase + SW128((uint32_t)(r * 128 + c * 2)));
            }
#pragma unroll
            for (int f = 0; f < 4; f++)
#pragma unroll
                for (int u = 0; u < 2; u++) {
                    MMA_F16(acc[f][2 * u],     A[f][0], A[f][1], A[f][2], A[f][3],
                            B[u][0], B[u][1]);
                    MMA_F16(acc[f][2 * u + 1], A[f][0], A[f][1], A[f][2], A[f][3],
                            B[u][2], B[u][3]);
                }
        }
    }

    if (mode == 1) {
        __half* Yh;
        int colmask;
        if (isPos) {
            Yh = Yp;
            colmask = 0x7FFFFFFF;          // identity (n < 1024 already)
        } else {
            const int buf = n0 >> 10;
            Yh = (__half*)Y0 + (size_t)buf * (NTOK * D_MODEL);
            colmask = 1023;
        }
#pragma unroll
        for (int f = 0; f < 4; f++) {
            const int r0 = m0 + wm * 64 + f * 16 + lq;
#pragma unroll
            for (int g = 0; g < 4; g++) {
                const int nc = n0 + wn * 32 + g * 8 + 2 * lr;
                const int col = nc & colmask;
                float2 bz = *(const float2*)(bias + nc);
                float2 v0, v1;
                v0.x = acc[f][g][0] + bz.x; v0.y = acc[f][g][1] + bz.y;
                v1.x = acc[f][g][2] + bz.x; v1.y = acc[f][g][3] + bz.y;
                *(uint32_t*)(Yh + (size_t)r0 * D_MODEL + col) = pack_half2(v0.x, v0.y);
                *(uint32_t*)(Yh + (size_t)(r0 + 8) * D_MODEL + col) = pack_half2(v1.x, v1.y);
            }
        }
    } else {
        float* Yf = (float*)Y0;
#pragma unroll
        for (int f = 0; f < 4; f++) {
            const int r0 = m0 + wm * 64 + f * 16 + lq;
#pragma unroll
            for (int g = 0; g < 4; g++) {
                const int nc = n0 + wn * 32 + g * 8 + 2 * lr;
                float2 bz = *(const float2*)(bias + nc);
                float2 v0, v1;
                v0.x = acc[f][g][0] + bz.x; v0.y = acc[f][g][1] + bz.y;
                v1.x = acc[f][g][2] + bz.x; v1.y = acc[f][g][3] + bz.y;
                *(float2*)(Yf + (size_t)r0 * D_MODEL + nc) = v0;
                *(float2*)(Yf + (size_t)(r0 + 8) * D_MODEL + nc) = v1;
            }
        }
    }
}

// ============================ fp16 flash attention ==========================
// BQ=128, BJ=128, dk=64. Q fragments add pos-projection p (fp32 add) at load.
#define BQ 128
#define BJ 128
#define KTILE_B (BJ * 64 * 2)            /* 16384 B per K (or V) stage */
#define AVB_OFF (2 * KTILE_B)
#define ATT_SMEM (4 * KTILE_B)           /* 65536 B */
#define SM_SCALE 0.18033688011112042f    /* 0.125 * log2(e) */
#define ONES_H2 0x3C003C00u              /* half2(1.0, 1.0) */

__global__ __launch_bounds__(256, 1) void flash_f16_kernel(
    const __half* __restrict__ Q, const __half* __restrict__ K,
    const __half* __restrict__ V, const __half* __restrict__ Ph,
    __half* __restrict__ O)
{
    extern __shared__ char smem[];
    const uint32_t sb = smem_u32(smem);
    const int tid = threadIdx.x;
    const int lane = tid & 31, w = tid >> 5;
    const int lq = lane >> 2, lr = lane & 3;
    const int grp = lane >> 3, lrow = lane & 7;
    const int qt = gridDim.x - 1 - blockIdx.x;   // heavy tiles first
    const int bh = blockIdx.y;
    const int b = bh >> 4, h = bh & 15;
    const int q0 = qt * BQ;
    const size_t base = ((size_t)b * SEQ) * D_MODEL + h * 64;

    uint32_t qa[4][4];
    {
        const int s0 = q0 + w * 16 + lq;         // within-batch token row
        const __half* q0p = Q + base + (size_t)s0 * D_MODEL;
        const __half* q1p = q0p + 8 * D_MODEL;
        const __half* p0p = Ph + (size_t)s0 * D_MODEL + h * 64;
        const __half* p1p = p0p + 8 * D_MODEL;
#pragma unroll
        for (int ks = 0; ks < 4; ks++) {
            const int c = ks * 16 + 2 * lr;
            qa[ks][0] = hadd2_f32(*(const uint32_t*)(q0p + c),
                                  *(const uint32_t*)(p0p + c));
            qa[ks][1] = hadd2_f32(*(const uint32_t*)(q1p + c),
                                  *(const uint32_t*)(p1p + c));
            qa[ks][2] = hadd2_f32(*(const uint32_t*)(q0p + c + 8),
                                  *(const uint32_t*)(p0p + c + 8));
            qa[ks][3] = hadd2_f32(*(const uint32_t*)(q1p + c + 8),
                                  *(const uint32_t*)(p1p + c + 8));
        }
    }

    float o[8][4];
#pragma unroll
    for (int g = 0; g < 8; g++)
#pragma unroll
        for (int e = 0; e < 4; e++) o[g][e] = 0.f;
    float m0 = -1e30f, m1 = -1e30f, l0 = 0.f, l1 = 0.f;

    const int nj = qt + 1;

#define LOAD_K(t_) do {                                                       \
    const __half* kg = K + base + (size_t)((t_) * BJ) * D_MODEL;              \
    const uint32_t kb = sb + ((t_) & 1) * KTILE_B;                            \
    _Pragma("unroll")                                                         \
    for (int i_ = 0; i_ < 4; i_++) {                                          \
        int seg = tid + (i_ << 8);          /* 0..1023 */                     \
        int row = seg >> 3, c16 = seg & 7;                                    \
        uint32_t off = SW128((uint32_t)(row * 128 + c16 * 16));               \
        CP_ASYNC16(kb + off, kg + (size_t)row * D_MODEL + c16 * 8);           \
    }                                                                         \
} while (0)

#define LOAD_V(t_) do {                                                       \
    const __half* vg = V + base + (size_t)((t_) * BJ) * D_MODEL;              \
    const uint32_t vb = sb + AVB_OFF + ((t_) & 1) * KTILE_B;                  \
    _Pragma("unroll")                                                         \
    for (int i_ = 0; i_ < 4; i_++) {                                          \
        int seg = tid + (i_ << 8);                                            \
        int row = seg >> 3, c16 = seg & 7;                                    \
        uint32_t off = SW128((uint32_t)(row * 128 + c16 * 16));               \
        CP_ASYNC16(vb + off, vg + (size_t)row * D_MODEL + c16 * 8);           \
    }                                                                         \
} while (0)

    LOAD_K(0); CP_COMMIT();
    LOAD_V(0); CP_COMMIT();

    const int qw = q0 + w * 16;
    const int qmax = qw + 15;

    for (int t = 0; t < nj; t++) {
        CP_WAIT(1);
        __syncthreads();
        if (t + 1 < nj) { LOAD_K(t + 1); CP_COMMIT(); }

        const uint32_t kbase = sb + (t & 1) * KTILE_B;
        const uint32_t vbase = sb + AVB_OFF + (t & 1) * KTILE_B;
        const int j0 = t * BJ;

        float s[16][4];
#pragma unroll
        for (int g = 0; g < 16; g++) {
            float init = ((j0 + g * 8) <= qmax) ? 0.f : -1e30f;
            s[g][0] = init; s[g][1] = init; s[g][2] = init; s[g][3] = init;
        }
#pragma unroll
        for (int ks = 0; ks < 4; ks++) {
            const int kc = ks * 16;
#pragma unroll
            for (int u = 0; u < 8; u++) {
                if ((j0 + u * 16) > qmax) continue;
                const int r = u * 16 + lrow + (grp >> 1) * 8;
                const int c = kc + (grp & 1) * 8;
                uint32_t b0, b1, b2, b3;
                LDSM4(b0, b1, b2, b3, kbase + SW128((uint32_t)(r * 128 + c * 2)));
                MMA_F16(s[2 * u],     qa[ks][0], qa[ks][1], qa[ks][2], qa[ks][3], b0, b1);
                MMA_F16(s[2 * u + 1], qa[ks][0], qa[ks][1], qa[ks][2], qa[ks][3], b2, b3);
            }
        }

#pragma unroll
        for (int g = 0; g < 16; g++) {
            s[g][0] *= SM_SCALE; s[g][1] *= SM_SCALE;
            s[g][2] *= SM_SCALE; s[g][3] *= SM_SCALE;
        }
        if (j0 + BJ - 1 > qw) {
            const int Q0 = qw + lq, Q1 = Q0 + 8;
#pragma unroll
            for (int g = 0; g < 16; g++) {
                const int jc = j0 + g * 8 + 2 * lr;
                if (jc     > Q0) s[g][0] = -1e30f;
                if (jc + 1 > Q0) s[g][1] = -1e30f;
                if (jc     > Q1) s[g][2] = -1e30f;
                if (jc + 1 > Q1) s[g][3] = -1e30f;
            }
        }

        float mx0 = -1e30f, mx1 = -1e30f;
#pragma unroll
        for (int g = 0; g < 16; g++) {
            mx0 = fmaxf(mx0, fmaxf(s[g][0], s[g][1]));
            mx1 = fmaxf(mx1, fmaxf(s[g][2], s[g][3]));
        }
        mx0 = fmaxf(mx0, __shfl_xor_sync(0xffffffffu, mx0, 1));
        mx0 = fmaxf(mx0, __shfl_xor_sync(0xffffffffu, mx0, 2));
        mx1 = fmaxf(mx1, __shfl_xor_sync(0xffffffffu, mx1, 1));
        mx1 = fmaxf(mx1, __shfl_xor_sync(0xffffffffu, mx1, 2));
        const float mn0 = fmaxf(m0, mx0), mn1 = fmaxf(m1, mx1);
        const float c0 = ex2(m0 - mn0), c1 = ex2(m1 - mn1);
        m0 = mn0; m1 = mn1;

        uint32_t pg0[16], pg1[16];
#pragma unroll
        for (int g = 0; g < 16; g++) {
            pg0[g] = ex2_h2(pack_half2(s[g][0] - mn0, s[g][1] - mn0));
            pg1[g] = ex2_h2(pack_half2(s[g][2] - mn1, s[g][3] - mn1));
        }

        float ls[4] = {0.f, 0.f, 0.f, 0.f};
#pragma unroll
        for (int kj = 0; kj < 8; kj++) {
            if ((j0 + kj * 16) > qmax) continue;
            MMA_F16(ls, pg0[2 * kj], pg1[2 * kj],
                    pg0[2 * kj + 1], pg1[2 * kj + 1], ONES_H2, ONES_H2);
        }
        l0 = l0 * c0 + ls[0];
        l1 = l1 * c1 + ls[2];
#pragma unroll
        for (int g = 0; g < 8; g++) {
            o[g][0] *= c0; o[g][1] *= c0;
            o[g][2] *= c1; o[g][3] *= c1;
        }

        if (t + 1 < nj) { CP_WAIT(1); } else { CP_WAIT(0); }
        __syncthreads();
        if (t + 1 < nj) { LOAD_V(t + 1); CP_COMMIT(); }

#pragma unroll
        for (int kj = 0; kj < 8; kj++) {
            if ((j0 + kj * 16) > qmax) continue;
            const uint32_t a0 = pg0[2 * kj],     a1 = pg1[2 * kj];
            const uint32_t a2 = pg0[2 * kj + 1], a3 = pg1[2 * kj + 1];
#pragma unroll
            for (int u = 0; u < 4; u++) {
                const int r = kj * 16 + lrow + (grp & 1) * 8;
                const int c = u * 16 + (grp >> 1) * 8;
                uint32_t b0, b1, b2, b3;
                LDSM4T(b0, b1, b2, b3, vbase + SW128((uint32_t)(r * 128 + c * 2)));
                MMA_F16(o[2 * u],     a0, a1, a2, a3, b0, b1);
                MMA_F16(o[2 * u + 1], a0, a1, a2, a3, b2, b3);
            }
        }
    }

    const float inv0 = 1.f / l0, inv1 = 1.f / l1;
    __half* o0 = O + base + (size_t)(qw + lq) * D_MODEL;
    __half* o1 = o0 + 8 * D_MODEL;
#pragma unroll
    for (int g = 0; g < 8; g++) {
        const int c = g * 8 + 2 * lr;
        *(uint32_t*)(o0 + c) = pack_half2(o[g][0] * inv0, o[g][1] * inv0);
        *(uint32_t*)(o1 + c) = pack_half2(o[g][2] * inv1, o[g][3] * inv1);
    }
}

// ---------------------------------------------------------------------------
extern "C" void kernel_launch(void* const* d_in, const int* in_sizes, int n_in,
                              void* d_out, int out_size)
{
    const float* x   = (const float*)d_in[0];
    const float* pos = (const float*)d_in[1];
    const float* Wq  = (const float*)d_in[2];
    const float* bq  = (const float*)d_in[3];
    const float* Wk  = (const float*)d_in[4];
    const float* bk  = (const float*)d_in[5];
    const float* Wv  = (const float*)d_in[6];
    const float* bv  = (const float*)d_in[7];
    const float* Wp  = (const float*)d_in[8];
    const float* bp  = (const float*)d_in[9];
    const float* Wo  = (const float*)d_in[10];
    const float* bo  = (const float*)d_in[11];
    float* out = (float*)d_out;

    __half *xh, *posh, *wh, *qkvh, *ctxh, *ph;
    float *bqkv;
    cudaGetSymbolAddress((void**)&xh,   g_xh);
    cudaGetSymbolAddress((void**)&posh, g_posh);
    cudaGetSymbolAddress((void**)&wh,   g_wh);
    cudaGetSymbolAddress((void**)&qkvh, g_qkvh);
    cudaGetSymbolAddress((void**)&ctxh, g_ctxh);
    cudaGetSymbolAddress((void**)&ph,   g_ph);
    cudaGetSymbolAddress((void**)&bqkv, g_bqkv);

    __half* wqkvh = wh;                                  // [3072, 1024]
    __half* woh   = wh + 3 * (size_t)D_MODEL * D_MODEL;
    __half* wph   = wh + 4 * (size_t)D_MODEL * D_MODEL;
    __half* qh = qkvh;
    __half* kh = qkvh + 1 * (size_t)NTOK * D_MODEL;
    __half* vh = qkvh + 2 * (size_t)NTOK * D_MODEL;

    static bool attr_done = false;
    if (!attr_done) {
        cudaFuncSetAttribute(gemm_f16_kernel,
                             cudaFuncAttributeMaxDynamicSharedMemorySize, SM_TOTAL);
        cudaFuncSetAttribute(flash_f16_kernel,
                             cudaFuncAttributeMaxDynamicSharedMemorySize, ATT_SMEM);
        attr_done = true;
    }

    // exact-cover pack (1 float4 per thread)
    pack_all_kernel<<<N4_TOT / 256, 256>>>(x, pos, Wq, Wk, Wv, Wo, Wp,
                                           bq, bk, bv, xh, posh, wh, bqkv);

    dim3 blk(512);
    // merged QKV [8192,3072] (bx 0..11) + pos [2048,1024] (bx == 12)
    gemm_f16_kernel<<<dim3(13, 64), blk, SM_TOTAL>>>(
        xh, wqkvh, bqkv, qkvh, 1, posh, wph, bp, ph);
    // attention -> ctx (fp16); Q fragments add p
    flash_f16_kernel<<<dim3(SEQ / BQ, BATCH * 16), 256, ATT_SMEM>>>(
        qh, kh, vh, ph, ctxh);
    // out = ctx @ Wo^T + bo (fp32)
    gemm_f16_kernel<<<dim3(4, 64), blk, SM_TOTAL>>>(
        ctxh, woh, bo, out, 0, nullptr, nullptr, nullptr, nullptr);
}